// round 5
// baseline (speedup 1.0000x reference)
#include <cuda_runtime.h>
#include <cstdint>

#define Bn 64
#define Nn 50000
#define Ln 8
#define En 100000
#define Un 20000
#define Gn 20000
#define Rn 64
#define Dn 16
#define Cn 2
#define QB 16            /* batch per quarter */
#define NQ 4             /* quarters */
#define QND (QB*Dn)      /* 256 floats per node per quarter */

// Scratch (device globals: allocation-free rule)
__device__ float g_h[(size_t)NQ * Nn * QND];   // 204.8 MB, [qtr][node][bq][d]; one quarter = 51.2MB
__device__ float g_agg[(size_t)Un * QND];      // 20.5 MB, per-(qtr,layer) dst values (reused)
__device__ int   g_csr[Ln * En];
__device__ int   g_off[Ln * (Un + 1)];
__device__ int   g_cnt[Ln * Un];
__device__ int   g_cur[Ln * Un];

__global__ void k_zero_h() {
    size_t i = (size_t)blockIdx.x * blockDim.x + threadIdx.x;
    size_t n4 = (size_t)NQ * Nn * QND / 4;
    if (i < n4) ((float4*)g_h)[i] = make_float4(0.f, 0.f, 0.f, 0.f);
}

__global__ void k_zero_int() {
    int i = blockIdx.x * blockDim.x + threadIdx.x;
    if (i < Ln * Un) { g_cnt[i] = 0; g_cur[i] = 0; }
}

// h[qtr][gene_map[g]][bq] = X[b,g] * w_in + b_in   (block = gene, thread = (b, q))
__global__ void k_gene(const float* __restrict__ X, const float* __restrict__ w_in,
                       const float* __restrict__ b_in, const int* __restrict__ gene_map) {
    int g = blockIdx.x;
    int t = threadIdx.x;
    int b = t >> 2, q = t & 3;
    int qtr = b >> 4, bq = b & 15;
    int node = gene_map[g];
    float x = X[(size_t)b * Gn + g];
    float4 w  = *(const float4*)(w_in + q * 4);
    float4 bi = *(const float4*)(b_in + q * 4);
    float4 v = make_float4(fmaf(x, w.x, bi.x), fmaf(x, w.y, bi.y),
                           fmaf(x, w.z, bi.z), fmaf(x, w.w, bi.w));
    *(float4*)(g_h + ((size_t)qtr * Nn + node) * QND + bq * Dn + q * 4) = v;
}

__global__ void k_hist(const int* __restrict__ dst_pos) {
    int i = blockIdx.x * blockDim.x + threadIdx.x;
    if (i < Ln * En) {
        int l = i / En;
        atomicAdd(&g_cnt[l * Un + dst_pos[i]], 1);
    }
}

// Exclusive scan of counts -> offsets, one block per layer.
__global__ void k_scan() {
    int l = blockIdx.x;
    const int* c = g_cnt + l * Un;
    int* o = g_off + l * (Un + 1);
    __shared__ int sh[1024];
    __shared__ int sbase;
    if (threadIdx.x == 0) sbase = 0;
    __syncthreads();
    for (int start = 0; start < Un; start += 1024) {
        int idx = start + (int)threadIdx.x;
        int v = (idx < Un) ? c[idx] : 0;
        sh[threadIdx.x] = v;
        __syncthreads();
        for (int st = 1; st < 1024; st <<= 1) {
            int tv = (threadIdx.x >= (unsigned)st) ? sh[threadIdx.x - st] : 0;
            __syncthreads();
            sh[threadIdx.x] += tv;
            __syncthreads();
        }
        if (idx < Un) o[idx] = sbase + sh[threadIdx.x] - v;  // exclusive
        __syncthreads();
        if (threadIdx.x == 0) sbase += sh[1023];
        __syncthreads();
    }
    if (threadIdx.x == 0) o[Un] = sbase;
}

__global__ void k_fill(const int* __restrict__ dst_pos) {
    int i = blockIdx.x * blockDim.x + threadIdx.x;
    if (i < Ln * En) {
        int l = i / En;
        int e = i - l * En;
        int u = dst_pos[i];
        int slot = g_off[l * (Un + 1) + u] + atomicAdd(&g_cur[l * Un + u], 1);
        g_csr[l * En + slot] = e;
    }
}

// Sort each bucket by edge id (deterministic sum order), then map edge id -> src node id.
__global__ void k_sortconv(const int* __restrict__ src) {
    int gid = blockIdx.x * blockDim.x + threadIdx.x;
    if (gid >= Ln * Un) return;
    int l = gid / Un;
    int u = gid - l * Un;
    int* seg = g_csr + l * En;
    int lo = g_off[l * (Un + 1) + u];
    int hi = g_off[l * (Un + 1) + u + 1];
    for (int i = lo + 1; i < hi; i++) {
        int key = seg[i];
        int j = i - 1;
        while (j >= lo && seg[j] > key) { seg[j + 1] = seg[j]; j--; }
        seg[j + 1] = key;
    }
    const int* sl = src + l * En;
    for (int i = lo; i < hi; i++) seg[i] = sl[seg[i]];
}

// 4 dst slots per block; 64 threads per slot = (bq = 0..15, q = 0..3).
// Phase 1: S[bq][4q..4q+3] = sum_edges h[qtr][src][bq][4q..] (1 LDG.128/edge, 2-deep prefetch)
// Phase 2: partial_j = sum_{k in q-slice} S[k]*W[k][j], all 16 j (32 FFMA2)
// Phase 3: smem reduce over q, + bias, tanh -> g_agg[u].
__global__ __launch_bounds__(256) void k_sumx(int l, int qtr, const float* __restrict__ W,
                                              const float* __restrict__ bias,
                                              const int* __restrict__ dstu) {
    int t = threadIdx.x;
    int u4 = t >> 6;
    int u = blockIdx.x * 4 + u4;
    int tt = t & 63;
    int bq = tt >> 2, q = tt & 3;

    const int* off = g_off + l * (Un + 1);
    int lo = off[u], hi = off[u + 1];
    int n = hi - lo;
    const int* e = g_csr + l * En + lo;
    const float* hq = g_h + (size_t)qtr * Nn * QND;

    // Phase 1
    float4 acc = make_float4(0.f, 0.f, 0.f, 0.f);
    float4 p0, p1;
    if (n > 0) p0 = *(const float4*)(hq + (size_t)e[0] * QND + tt * 4);
    if (n > 1) p1 = *(const float4*)(hq + (size_t)e[1] * QND + tt * 4);
    for (int i = 0; i < n; i++) {
        float4 v = p0;
        p0 = p1;
        if (i + 2 < n) p1 = *(const float4*)(hq + (size_t)e[i + 2] * QND + tt * 4);
        acc.x += v.x; acc.y += v.y; acc.z += v.z; acc.w += v.w;
    }
    float sv[4] = { acc.x, acc.y, acc.z, acc.w };

    // Phase 2: partial over this thread's k-slice (rows 4q..4q+3), all 16 outputs.
    unsigned long long pa[8];
    #pragma unroll
    for (int jp = 0; jp < 8; jp++) pa[jp] = 0ull;
    const float* Wl = W + l * Dn * Dn;
    #pragma unroll
    for (int kk = 0; kk < 4; kk++) {
        int row = (q << 2) + kk;
        ulonglong2 wa = *(const ulonglong2*)(Wl + row * Dn);
        ulonglong2 wb = *(const ulonglong2*)(Wl + row * Dn + 4);
        ulonglong2 wc = *(const ulonglong2*)(Wl + row * Dn + 8);
        ulonglong2 wd = *(const ulonglong2*)(Wl + row * Dn + 12);
        unsigned long long s2;
        asm("mov.b64 %0, {%1, %1};" : "=l"(s2) : "f"(sv[kk]));
        asm("fma.rn.f32x2 %0, %1, %2, %0;" : "+l"(pa[0]) : "l"(s2), "l"(wa.x));
        asm("fma.rn.f32x2 %0, %1, %2, %0;" : "+l"(pa[1]) : "l"(s2), "l"(wa.y));
        asm("fma.rn.f32x2 %0, %1, %2, %0;" : "+l"(pa[2]) : "l"(s2), "l"(wb.x));
        asm("fma.rn.f32x2 %0, %1, %2, %0;" : "+l"(pa[3]) : "l"(s2), "l"(wb.y));
        asm("fma.rn.f32x2 %0, %1, %2, %0;" : "+l"(pa[4]) : "l"(s2), "l"(wc.x));
        asm("fma.rn.f32x2 %0, %1, %2, %0;" : "+l"(pa[5]) : "l"(s2), "l"(wc.y));
        asm("fma.rn.f32x2 %0, %1, %2, %0;" : "+l"(pa[6]) : "l"(s2), "l"(wd.x));
        asm("fma.rn.f32x2 %0, %1, %2, %0;" : "+l"(pa[7]) : "l"(s2), "l"(wd.y));
    }

    // Phase 3: reduce over q, bias + tanh, store to agg.
    __shared__ float sred[4][4][16][17];
    #pragma unroll
    for (int jp = 0; jp < 8; jp++) {
        float flo, fhi;
        asm("mov.b64 {%0, %1}, %2;" : "=f"(flo), "=f"(fhi) : "l"(pa[jp]));
        sred[u4][q][bq][jp * 2]     = flo;
        sred[u4][q][bq][jp * 2 + 1] = fhi;
    }
    __syncthreads();

    float r0 = 0.f, r1 = 0.f, r2 = 0.f, r3 = 0.f;
    int j0 = q << 2;
    #pragma unroll
    for (int qq = 0; qq < 4; qq++) {
        r0 += sred[u4][qq][bq][j0 + 0];
        r1 += sred[u4][qq][bq][j0 + 1];
        r2 += sred[u4][qq][bq][j0 + 2];
        r3 += sred[u4][qq][bq][j0 + 3];
    }

    int node = dstu[u];
    float4 bi = *(const float4*)(bias + (size_t)node * Dn + j0);
    float4 outv = make_float4(tanhf(r0 + bi.x), tanhf(r1 + bi.y),
                              tanhf(r2 + bi.z), tanhf(r3 + bi.w));
    *(float4*)(g_agg + (size_t)u * QND + tt * 4) = outv;
}

// Commit: h[qtr][dst_unique[u]] = agg[u]. 4 slots per block.
__global__ void k_scat(int qtr, const int* __restrict__ dstu) {
    int t = threadIdx.x;
    int u = blockIdx.x * 4 + (t >> 6);
    int tt = t & 63;
    int node = dstu[u];
    *(float4*)(g_h + ((size_t)qtr * Nn + node) * QND + tt * 4) =
        *(const float4*)(g_agg + (size_t)u * QND + tt * 4);
}

// out[b,c] = sum_{r,j} h[root[r]][b][j] * W_head[c][r*16+j] + b_head[c]
__global__ void k_head(const int* __restrict__ roots, const float* __restrict__ Wh,
                       const float* __restrict__ bh, float* __restrict__ out) {
    int b = blockIdx.x;
    int qtr = b >> 4, bq = b & 15;
    int t = threadIdx.x;
    float a0 = 0.f, a1 = 0.f;
    for (int i = t; i < Rn * Dn; i += 256) {
        int r = i >> 4, j = i & 15;
        float f = g_h[((size_t)qtr * Nn + roots[r]) * QND + bq * Dn + j];
        a0 = fmaf(f, Wh[i], a0);
        a1 = fmaf(f, Wh[Rn * Dn + i], a1);
    }
    __shared__ float s0[256], s1[256];
    s0[t] = a0; s1[t] = a1;
    __syncthreads();
    for (int st = 128; st > 0; st >>= 1) {
        if (t < st) { s0[t] += s0[t + st]; s1[t] += s1[t + st]; }
        __syncthreads();
    }
    if (t == 0) {
        out[b * Cn + 0] = s0[0] + bh[0];
        out[b * Cn + 1] = s1[0] + bh[1];
    }
}

extern "C" void kernel_launch(void* const* d_in, const int* in_sizes, int n_in,
                              void* d_out, int out_size) {
    (void)in_sizes; (void)n_in; (void)out_size;
    const float* X          = (const float*)d_in[0];
    const float* w_in       = (const float*)d_in[1];
    const float* b_in       = (const float*)d_in[2];
    const float* W          = (const float*)d_in[3];
    const float* bias       = (const float*)d_in[4];
    const float* W_head     = (const float*)d_in[5];
    const float* b_head     = (const float*)d_in[6];
    const int*   gene_map   = (const int*)d_in[7];
    const int*   src        = (const int*)d_in[8];
    const int*   dst_pos    = (const int*)d_in[9];
    const int*   dst_unique = (const int*)d_in[10];
    const int*   root_ids   = (const int*)d_in[11];
    float* out = (float*)d_out;

    {
        size_t n4 = (size_t)NQ * Nn * QND / 4;
        k_zero_h<<<(unsigned)((n4 + 255) / 256), 256>>>();
    }
    k_zero_int<<<(Ln * Un + 255) / 256, 256>>>();
    k_gene<<<Gn, 256>>>(X, w_in, b_in, gene_map);

    // Batched CSR build for all 8 layers (depends only on dst_pos / src)
    k_hist<<<(Ln * En + 255) / 256, 256>>>(dst_pos);
    k_scan<<<Ln, 1024>>>();
    k_fill<<<(Ln * En + 255) / 256, 256>>>(dst_pos);
    k_sortconv<<<(Ln * Un + 255) / 256, 256>>>(src);

    // Quarter-major loop: keeps one 51MB h-quarter (plus 20MB agg) L2-resident
    // across all 8 layers of that quarter.
    for (int qtr = 0; qtr < NQ; qtr++) {
        for (int l = 0; l < Ln; l++) {
            k_sumx<<<Un / 4, 256>>>(l, qtr, W, bias, dst_unique + l * Un);
            k_scat<<<Un / 4, 256>>>(qtr, dst_unique + l * Un);
        }
    }

    k_head<<<Bn, 256>>>(root_ids, W_head, b_head, out);
}

// round 6
// speedup vs baseline: 1.0296x; 1.0296x over previous
#include <cuda_runtime.h>
#include <cstdint>

#define Bn 64
#define Nn 50000
#define Ln 8
#define En 100000
#define Un 20000
#define Gn 20000
#define Rn 64
#define Dn 16
#define Cn 2
#define ND (Bn*Dn)                /* 1024 floats per row */
#define NROWS (Nn + Ln*Un)        /* 210000 rows: h then per-layer outputs */

// Scratch (device globals: allocation-free rule)
__device__ float g_all[(size_t)NROWS * ND];   // ~860 MB unified value store
__device__ int   g_loc[Nn];                   // node -> current row index in g_all
__device__ int   g_csr[Ln * En];              // after setup: resolved source ROW ids
__device__ int   g_off[Ln * (Un + 1)];
__device__ int   g_cnt[Ln * Un];
__device__ int   g_cur[Ln * Un];

__global__ void k_zero_h() {
    size_t i = (size_t)blockIdx.x * blockDim.x + threadIdx.x;
    size_t n4 = (size_t)Nn * ND / 4;   // only the h region needs zeroing
    if (i < n4) ((float4*)g_all)[i] = make_float4(0.f, 0.f, 0.f, 0.f);
}

__global__ void k_zero_int() {
    int i = blockIdx.x * blockDim.x + threadIdx.x;
    if (i < Ln * Un) { g_cnt[i] = 0; g_cur[i] = 0; }
    if (i < Nn) g_loc[i] = i;          // node initially lives at its own h row
}

// h[gene_map[g]] = X[b,g] * w_in + b_in  (block = gene, thread = (b, j0))
__global__ void k_gene(const float* __restrict__ X, const float* __restrict__ w_in,
                       const float* __restrict__ b_in, const int* __restrict__ gene_map) {
    int g = blockIdx.x;
    int t = threadIdx.x;
    int b = t >> 2, j0 = (t & 3) << 2;
    int node = gene_map[g];
    float x = X[(size_t)b * Gn + g];
    float4 w  = *(const float4*)(w_in + j0);
    float4 bi = *(const float4*)(b_in + j0);
    float4 v = make_float4(fmaf(x, w.x, bi.x), fmaf(x, w.y, bi.y),
                           fmaf(x, w.z, bi.z), fmaf(x, w.w, bi.w));
    *(float4*)(g_all + (size_t)node * ND + t * 4) = v;
}

__global__ void k_hist(const int* __restrict__ dst_pos) {
    int i = blockIdx.x * blockDim.x + threadIdx.x;
    if (i < Ln * En) {
        int l = i / En;
        atomicAdd(&g_cnt[l * Un + dst_pos[i]], 1);
    }
}

// Exclusive scan of counts -> offsets, one block per layer.
__global__ void k_scan() {
    int l = blockIdx.x;
    const int* c = g_cnt + l * Un;
    int* o = g_off + l * (Un + 1);
    __shared__ int sh[1024];
    __shared__ int sbase;
    if (threadIdx.x == 0) sbase = 0;
    __syncthreads();
    for (int start = 0; start < Un; start += 1024) {
        int idx = start + (int)threadIdx.x;
        int v = (idx < Un) ? c[idx] : 0;
        sh[threadIdx.x] = v;
        __syncthreads();
        for (int st = 1; st < 1024; st <<= 1) {
            int tv = (threadIdx.x >= (unsigned)st) ? sh[threadIdx.x - st] : 0;
            __syncthreads();
            sh[threadIdx.x] += tv;
            __syncthreads();
        }
        if (idx < Un) o[idx] = sbase + sh[threadIdx.x] - v;  // exclusive
        __syncthreads();
        if (threadIdx.x == 0) sbase += sh[1023];
        __syncthreads();
    }
    if (threadIdx.x == 0) o[Un] = sbase;
}

__global__ void k_fill(const int* __restrict__ dst_pos) {
    int i = blockIdx.x * blockDim.x + threadIdx.x;
    if (i < Ln * En) {
        int l = i / En;
        int e = i - l * En;
        int u = dst_pos[i];
        int slot = g_off[l * (Un + 1) + u] + atomicAdd(&g_cur[l * Un + u], 1);
        g_csr[l * En + slot] = e;
    }
}

// Sort each bucket by edge id (deterministic sum order), then map edge id -> src node id.
__global__ void k_sortconv(const int* __restrict__ src) {
    int gid = blockIdx.x * blockDim.x + threadIdx.x;
    if (gid >= Ln * Un) return;
    int l = gid / Un;
    int u = gid - l * Un;
    int* seg = g_csr + l * En;
    int lo = g_off[l * (Un + 1) + u];
    int hi = g_off[l * (Un + 1) + u + 1];
    for (int i = lo + 1; i < hi; i++) {
        int key = seg[i];
        int j = i - 1;
        while (j >= lo && seg[j] > key) { seg[j + 1] = seg[j]; j--; }
        seg[j + 1] = key;
    }
    const int* sl = src + l * En;
    for (int i = lo; i < hi; i++) seg[i] = sl[seg[i]];
}

// Setup: remap layer-l CSR entries from node ids to resolved row ids (pre-update snapshot).
__global__ void k_resolve(int l) {
    int i = blockIdx.x * blockDim.x + threadIdx.x;
    if (i < En) {
        int* p = g_csr + l * En + i;
        *p = g_loc[*p];
    }
}

// Setup: after layer l, dst nodes live at row Nn + l*Un + u.
__global__ void k_loc(int l, const int* __restrict__ dstu) {
    int u = blockIdx.x * blockDim.x + threadIdx.x;
    if (u < Un) g_loc[dstu[u]] = Nn + l * Un + u;
}

// One block per dst slot u. Thread = (b = t>>2, q = t&3).
// Phase 1: S[b][4q..4q+3] = sum_edges g_all[row][b][4q..]  (1 LDG.128/edge, 2-deep prefetch)
// Phase 2: partial_j = sum_{k in q-slice} S[k]*W[k][j], all 16 j  (32 FFMA2)
// Phase 3: smem reduce over q, + bias, tanh -> own output row (no aliasing).
__global__ __launch_bounds__(256) void k_gather(int l, const float* __restrict__ W,
                                                const float* __restrict__ bias,
                                                const int* __restrict__ dstu) {
    int u = blockIdx.x;
    int t = threadIdx.x;
    int b = t >> 2, q = t & 3;

    const int* off = g_off + l * (Un + 1);
    int lo = off[u], hi = off[u + 1];
    int n = hi - lo;
    const int* e = g_csr + l * En + lo;

    // Phase 1: direct gather from unified store (row ids pre-resolved).
    float4 acc = make_float4(0.f, 0.f, 0.f, 0.f);
    float4 p0, p1;
    if (n > 0) p0 = *(const float4*)(g_all + (size_t)e[0] * ND + t * 4);
    if (n > 1) p1 = *(const float4*)(g_all + (size_t)e[1] * ND + t * 4);
    for (int i = 0; i < n; i++) {
        float4 v = p0;
        p0 = p1;
        if (i + 2 < n) p1 = *(const float4*)(g_all + (size_t)e[i + 2] * ND + t * 4);
        acc.x += v.x; acc.y += v.y; acc.z += v.z; acc.w += v.w;
    }
    float sv[4] = { acc.x, acc.y, acc.z, acc.w };

    // Phase 2: partial transform over this thread's k-slice (rows 4q..4q+3), all 16 outputs.
    unsigned long long pa[8];
    #pragma unroll
    for (int jp = 0; jp < 8; jp++) pa[jp] = 0ull;
    const float* Wl = W + l * Dn * Dn;
    #pragma unroll
    for (int kk = 0; kk < 4; kk++) {
        int row = (q << 2) + kk;
        ulonglong2 wa = *(const ulonglong2*)(Wl + row * Dn);
        ulonglong2 wb = *(const ulonglong2*)(Wl + row * Dn + 4);
        ulonglong2 wc = *(const ulonglong2*)(Wl + row * Dn + 8);
        ulonglong2 wd = *(const ulonglong2*)(Wl + row * Dn + 12);
        unsigned long long s2;
        asm("mov.b64 %0, {%1, %1};" : "=l"(s2) : "f"(sv[kk]));
        asm("fma.rn.f32x2 %0, %1, %2, %0;" : "+l"(pa[0]) : "l"(s2), "l"(wa.x));
        asm("fma.rn.f32x2 %0, %1, %2, %0;" : "+l"(pa[1]) : "l"(s2), "l"(wa.y));
        asm("fma.rn.f32x2 %0, %1, %2, %0;" : "+l"(pa[2]) : "l"(s2), "l"(wb.x));
        asm("fma.rn.f32x2 %0, %1, %2, %0;" : "+l"(pa[3]) : "l"(s2), "l"(wb.y));
        asm("fma.rn.f32x2 %0, %1, %2, %0;" : "+l"(pa[4]) : "l"(s2), "l"(wc.x));
        asm("fma.rn.f32x2 %0, %1, %2, %0;" : "+l"(pa[5]) : "l"(s2), "l"(wc.y));
        asm("fma.rn.f32x2 %0, %1, %2, %0;" : "+l"(pa[6]) : "l"(s2), "l"(wd.x));
        asm("fma.rn.f32x2 %0, %1, %2, %0;" : "+l"(pa[7]) : "l"(s2), "l"(wd.y));
    }

    // Phase 3: cross-q reduce in smem, bias + tanh, store own output row.
    __shared__ float sred[4][64][18];
    #pragma unroll
    for (int jp = 0; jp < 8; jp++) {
        float flo, fhi;
        asm("mov.b64 {%0, %1}, %2;" : "=f"(flo), "=f"(fhi) : "l"(pa[jp]));
        sred[q][b][jp * 2]     = flo;
        sred[q][b][jp * 2 + 1] = fhi;
    }
    __syncthreads();

    int j0 = q << 2;
    float r0 = 0.f, r1 = 0.f, r2 = 0.f, r3 = 0.f;
    #pragma unroll
    for (int qq = 0; qq < 4; qq++) {
        r0 += sred[qq][b][j0 + 0];
        r1 += sred[qq][b][j0 + 1];
        r2 += sred[qq][b][j0 + 2];
        r3 += sred[qq][b][j0 + 3];
    }

    int node = dstu[u];
    float4 bi = *(const float4*)(bias + (size_t)node * Dn + j0);
    float4 outv = make_float4(tanhf(r0 + bi.x), tanhf(r1 + bi.y),
                              tanhf(r2 + bi.z), tanhf(r3 + bi.w));
    *(float4*)(g_all + (size_t)(Nn + l * Un + u) * ND + t * 4) = outv;
}

// out[b,c] = sum_{r,j} val(root[r])[b][j] * W_head[c][r*16+j] + b_head[c]
// g_loc holds the FINAL row mapping after all 8 setup k_loc passes.
__global__ void k_head(const int* __restrict__ roots, const float* __restrict__ Wh,
                       const float* __restrict__ bh, float* __restrict__ out) {
    int b = blockIdx.x;
    int t = threadIdx.x;
    float a0 = 0.f, a1 = 0.f;
    for (int i = t; i < Rn * Dn; i += 256) {
        int r = i >> 4, j = i & 15;
        int row = g_loc[roots[r]];
        float f = g_all[(size_t)row * ND + (b << 4) + j];
        a0 = fmaf(f, Wh[i], a0);
        a1 = fmaf(f, Wh[Rn * Dn + i], a1);
    }
    __shared__ float s0[256], s1[256];
    s0[t] = a0; s1[t] = a1;
    __syncthreads();
    for (int st = 128; st > 0; st >>= 1) {
        if (t < st) { s0[t] += s0[t + st]; s1[t] += s1[t + st]; }
        __syncthreads();
    }
    if (t == 0) {
        out[b * Cn + 0] = s0[0] + bh[0];
        out[b * Cn + 1] = s1[0] + bh[1];
    }
}

extern "C" void kernel_launch(void* const* d_in, const int* in_sizes, int n_in,
                              void* d_out, int out_size) {
    (void)in_sizes; (void)n_in; (void)out_size;
    const float* X          = (const float*)d_in[0];
    const float* w_in       = (const float*)d_in[1];
    const float* b_in       = (const float*)d_in[2];
    const float* W          = (const float*)d_in[3];
    const float* bias       = (const float*)d_in[4];
    const float* W_head     = (const float*)d_in[5];
    const float* b_head     = (const float*)d_in[6];
    const int*   gene_map   = (const int*)d_in[7];
    const int*   src        = (const int*)d_in[8];
    const int*   dst_pos    = (const int*)d_in[9];
    const int*   dst_unique = (const int*)d_in[10];
    const int*   root_ids   = (const int*)d_in[11];
    float* out = (float*)d_out;

    {
        size_t n4 = (size_t)Nn * ND / 4;
        k_zero_h<<<(unsigned)((n4 + 255) / 256), 256>>>();
    }
    k_zero_int<<<(Ln * Un + 255) / 256, 256>>>();
    k_gene<<<Gn, 256>>>(X, w_in, b_in, gene_map);

    // Batched CSR build for all 8 layers (depends only on dst_pos / src)
    k_hist<<<(Ln * En + 255) / 256, 256>>>(dst_pos);
    k_scan<<<Ln, 1024>>>();
    k_fill<<<(Ln * En + 255) / 256, 256>>>(dst_pos);
    k_sortconv<<<(Ln * Un + 255) / 256, 256>>>(src);

    // Resolve CSR node ids -> row ids layer by layer (snapshot semantics).
    for (int l = 0; l < Ln; l++) {
        k_resolve<<<(En + 255) / 256, 256>>>(l);
        k_loc<<<(Un + 255) / 256, 256>>>(l, dst_unique + l * Un);
    }

    // Main loop: one fused gather+transform kernel per layer.
    for (int l = 0; l < Ln; l++) {
        k_gather<<<Un, 256>>>(l, W, bias, dst_unique + l * Un);
    }

    k_head<<<Bn, 256>>>(root_ids, W_head, b_head, out);
}

// round 7
// speedup vs baseline: 1.8448x; 1.7917x over previous
#include <cuda_runtime.h>
#include <cstdint>

#define Bn 64
#define Nn 50000
#define Ln 8
#define En 100000
#define Un 20000
#define Gn 20000
#define Rn 64
#define Dn 16
#define Cn 2
#define ND (Bn*Dn)   /* 1024 floats per node row */
#define NPB 8        /* agg rows per block in k_xf2 */

// Scratch (device globals: allocation-free rule)
__device__ float g_h[(size_t)Nn * ND];     // ~204.8 MB, [node][b][d], updated in place
__device__ float g_agg[(size_t)Un * ND];   // ~81.9 MB, per-layer edge sums (reused)
__device__ int   g_csr[Ln * En];
__device__ int   g_off[Ln * (Un + 1)];
__device__ int   g_cnt[Ln * Un];
__device__ int   g_cur[Ln * Un];

__global__ void k_zero_h() {
    size_t i = (size_t)blockIdx.x * blockDim.x + threadIdx.x;
    size_t n4 = (size_t)Nn * ND / 4;
    if (i < n4) ((float4*)g_h)[i] = make_float4(0.f, 0.f, 0.f, 0.f);
}

__global__ void k_zero_int() {
    int i = blockIdx.x * blockDim.x + threadIdx.x;
    if (i < Ln * Un) { g_cnt[i] = 0; g_cur[i] = 0; }
}

// h[gene_map[g]] = X[b,g] * w_in + b_in  (block = gene, thread = (b, j0))
__global__ void k_gene(const float* __restrict__ X, const float* __restrict__ w_in,
                       const float* __restrict__ b_in, const int* __restrict__ gene_map) {
    int g = blockIdx.x;
    int t = threadIdx.x;
    int b = t >> 2, j0 = (t & 3) << 2;
    int node = gene_map[g];
    float x = X[(size_t)b * Gn + g];
    float4 w  = *(const float4*)(w_in + j0);
    float4 bi = *(const float4*)(b_in + j0);
    float4 v = make_float4(fmaf(x, w.x, bi.x), fmaf(x, w.y, bi.y),
                           fmaf(x, w.z, bi.z), fmaf(x, w.w, bi.w));
    *(float4*)(g_h + (size_t)node * ND + t * 4) = v;
}

__global__ void k_hist(const int* __restrict__ dst_pos) {
    int i = blockIdx.x * blockDim.x + threadIdx.x;
    if (i < Ln * En) {
        int l = i / En;
        atomicAdd(&g_cnt[l * Un + dst_pos[i]], 1);
    }
}

// Exclusive scan of counts -> offsets, one block per layer.
__global__ void k_scan() {
    int l = blockIdx.x;
    const int* c = g_cnt + l * Un;
    int* o = g_off + l * (Un + 1);
    __shared__ int sh[1024];
    __shared__ int sbase;
    if (threadIdx.x == 0) sbase = 0;
    __syncthreads();
    for (int start = 0; start < Un; start += 1024) {
        int idx = start + (int)threadIdx.x;
        int v = (idx < Un) ? c[idx] : 0;
        sh[threadIdx.x] = v;
        __syncthreads();
        for (int st = 1; st < 1024; st <<= 1) {
            int tv = (threadIdx.x >= (unsigned)st) ? sh[threadIdx.x - st] : 0;
            __syncthreads();
            sh[threadIdx.x] += tv;
            __syncthreads();
        }
        if (idx < Un) o[idx] = sbase + sh[threadIdx.x] - v;  // exclusive
        __syncthreads();
        if (threadIdx.x == 0) sbase += sh[1023];
        __syncthreads();
    }
    if (threadIdx.x == 0) o[Un] = sbase;
}

__global__ void k_fill(const int* __restrict__ dst_pos) {
    int i = blockIdx.x * blockDim.x + threadIdx.x;
    if (i < Ln * En) {
        int l = i / En;
        int e = i - l * En;
        int u = dst_pos[i];
        int slot = g_off[l * (Un + 1) + u] + atomicAdd(&g_cur[l * Un + u], 1);
        g_csr[l * En + slot] = e;
    }
}

// Sort each bucket by edge id (deterministic sum order), then map edge id -> src node id.
__global__ void k_sortconv(const int* __restrict__ src) {
    int gid = blockIdx.x * blockDim.x + threadIdx.x;
    if (gid >= Ln * Un) return;
    int l = gid / Un;
    int u = gid - l * Un;
    int* seg = g_csr + l * En;
    int lo = g_off[l * (Un + 1) + u];
    int hi = g_off[l * (Un + 1) + u + 1];
    for (int i = lo + 1; i < hi; i++) {
        int key = seg[i];
        int j = i - 1;
        while (j >= lo && seg[j] > key) { seg[j + 1] = seg[j]; j--; }
        seg[j + 1] = key;
    }
    const int* sl = src + l * En;
    for (int i = lo; i < hi; i++) seg[i] = sl[seg[i]];
}

// Pure edge-sum: agg[u][half] = sum_edges h[src][half].
// Block = (u, half); 128 threads cover 512 floats (half a row).
// Lean: ~20 regs, no smem, no sync -> deep occupancy + MLP.
__global__ __launch_bounds__(128) void k_gsum(int l) {
    int u = blockIdx.x;
    int tt = threadIdx.x;
    size_t col = ((size_t)blockIdx.y << 9) + (tt << 2);

    const int* off = g_off + l * (Un + 1);
    int lo = off[u], hi = off[u + 1];
    int n = hi - lo;
    const int* e = g_csr + l * En + lo;

    float4 acc = make_float4(0.f, 0.f, 0.f, 0.f);
    float4 p0, p1;
    if (n > 0) p0 = *(const float4*)(g_h + (size_t)e[0] * ND + col);
    if (n > 1) p1 = *(const float4*)(g_h + (size_t)e[1] * ND + col);
    for (int i = 0; i < n; i++) {
        float4 v = p0;
        p0 = p1;
        if (i + 2 < n) p1 = *(const float4*)(g_h + (size_t)e[i + 2] * ND + col);
        acc.x += v.x; acc.y += v.y; acc.z += v.z; acc.w += v.w;
    }
    // evict-first store: don't let agg pollute L2 (h-half should stay resident)
    __stcs((float4*)(g_agg + (size_t)u * ND + col), acc);
}

// Streaming transform of the 20K agg rows: h[dstu[u]] = tanh(agg[u] @ W + bias[dstu[u]]).
// Block handles NPB consecutive agg rows; thread = (b, q); W in registers.
__global__ __launch_bounds__(256, 2) void k_xf2(int l, const float* __restrict__ W,
                                                const float* __restrict__ bias,
                                                const int* __restrict__ dstu) {
    const float* Wl = W + l * Dn * Dn;
    int t = threadIdx.x;
    int b = t >> 2, q = t & 3;
    int j0 = q << 2;
    int u0 = blockIdx.x * NPB;

    // W[k][j0..j0+3] as two packed f32x2 pairs per k, in registers.
    unsigned long long w01[16], w23[16];
    #pragma unroll
    for (int k = 0; k < 16; k++) {
        ulonglong2 wp = *(const ulonglong2*)(Wl + k * Dn + j0);
        w01[k] = wp.x;
        w23[k] = wp.y;
    }

    const float4* ap = (const float4*)(g_agg + (size_t)u0 * ND + (b << 4));
    float4 c0 = ap[0], c1 = ap[1], c2 = ap[2], c3 = ap[3];

    #pragma unroll
    for (int nn = 0; nn < NPB; nn++) {
        float4 v0 = c0, v1 = c1, v2 = c2, v3 = c3;
        if (nn + 1 < NPB) {
            const float4* np = (const float4*)(g_agg + (size_t)(u0 + nn + 1) * ND + (b << 4));
            c0 = np[0]; c1 = np[1]; c2 = np[2]; c3 = np[3];
        }
        unsigned long long acc01 = 0ull, acc23 = 0ull;
        #define XF_STEP(kk, hval) { unsigned long long hk2_; \
            asm("mov.b64 %0, {%1, %1};" : "=l"(hk2_) : "f"(hval)); \
            asm("fma.rn.f32x2 %0, %1, %2, %0;" : "+l"(acc01) : "l"(hk2_), "l"(w01[kk])); \
            asm("fma.rn.f32x2 %0, %1, %2, %0;" : "+l"(acc23) : "l"(hk2_), "l"(w23[kk])); }
        XF_STEP(0,  v0.x) XF_STEP(1,  v0.y) XF_STEP(2,  v0.z) XF_STEP(3,  v0.w)
        XF_STEP(4,  v1.x) XF_STEP(5,  v1.y) XF_STEP(6,  v1.z) XF_STEP(7,  v1.w)
        XF_STEP(8,  v2.x) XF_STEP(9,  v2.y) XF_STEP(10, v2.z) XF_STEP(11, v2.w)
        XF_STEP(12, v3.x) XF_STEP(13, v3.y) XF_STEP(14, v3.z) XF_STEP(15, v3.w)
        #undef XF_STEP

        int node = dstu[u0 + nn];
        float4 bi = *(const float4*)(bias + (size_t)node * Dn + j0);
        float r0, r1, r2, r3;
        asm("mov.b64 {%0, %1}, %2;" : "=f"(r0), "=f"(r1) : "l"(acc01));
        asm("mov.b64 {%0, %1}, %2;" : "=f"(r2), "=f"(r3) : "l"(acc23));
        float4 outv = make_float4(tanhf(r0 + bi.x), tanhf(r1 + bi.y),
                                  tanhf(r2 + bi.z), tanhf(r3 + bi.w));
        *(float4*)(g_h + (size_t)node * ND + t * 4) = outv;
    }
}

// out[b,c] = sum_{r,j} h[root[r]][b][j] * W_head[c][r*16+j] + b_head[c]
__global__ void k_head(const int* __restrict__ roots, const float* __restrict__ Wh,
                       const float* __restrict__ bh, float* __restrict__ out) {
    int b = blockIdx.x;
    int t = threadIdx.x;
    float a0 = 0.f, a1 = 0.f;
    for (int i = t; i < Rn * Dn; i += 256) {
        int r = i >> 4, j = i & 15;
        float f = g_h[(size_t)roots[r] * ND + (b << 4) + j];
        a0 = fmaf(f, Wh[i], a0);
        a1 = fmaf(f, Wh[Rn * Dn + i], a1);
    }
    __shared__ float s0[256], s1[256];
    s0[t] = a0; s1[t] = a1;
    __syncthreads();
    for (int st = 128; st > 0; st >>= 1) {
        if (t < st) { s0[t] += s0[t + st]; s1[t] += s1[t + st]; }
        __syncthreads();
    }
    if (t == 0) {
        out[b * Cn + 0] = s0[0] + bh[0];
        out[b * Cn + 1] = s1[0] + bh[1];
    }
}

extern "C" void kernel_launch(void* const* d_in, const int* in_sizes, int n_in,
                              void* d_out, int out_size) {
    (void)in_sizes; (void)n_in; (void)out_size;
    const float* X          = (const float*)d_in[0];
    const float* w_in       = (const float*)d_in[1];
    const float* b_in       = (const float*)d_in[2];
    const float* W          = (const float*)d_in[3];
    const float* bias       = (const float*)d_in[4];
    const float* W_head     = (const float*)d_in[5];
    const float* b_head     = (const float*)d_in[6];
    const int*   gene_map   = (const int*)d_in[7];
    const int*   src        = (const int*)d_in[8];
    const int*   dst_pos    = (const int*)d_in[9];
    const int*   dst_unique = (const int*)d_in[10];
    const int*   root_ids   = (const int*)d_in[11];
    float* out = (float*)d_out;

    {
        size_t n4 = (size_t)Nn * ND / 4;
        k_zero_h<<<(unsigned)((n4 + 255) / 256), 256>>>();
    }
    k_zero_int<<<(Ln * Un + 255) / 256, 256>>>();
    k_gene<<<Gn, 256>>>(X, w_in, b_in, gene_map);

    // Batched CSR build for all 8 layers (depends only on dst_pos / src)
    k_hist<<<(Ln * En + 255) / 256, 256>>>(dst_pos);
    k_scan<<<Ln, 1024>>>();
    k_fill<<<(Ln * En + 255) / 256, 256>>>(dst_pos);
    k_sortconv<<<(Ln * Un + 255) / 256, 256>>>(src);

    for (int l = 0; l < Ln; l++) {
        k_gsum<<<dim3(Un, 2), 128>>>(l);                       // sum raw h rows (B-halved for L2)
        k_xf2<<<Un / NPB, 256>>>(l, W, bias, dst_unique + l * Un);  // transform 20K rows + scatter
    }

    k_head<<<Bn, 256>>>(root_ids, W_head, b_head, out);
}

// round 8
// speedup vs baseline: 1.9353x; 1.0491x over previous
#include <cuda_runtime.h>
#include <cstdint>

#define Bn 64
#define Nn 50000
#define Ln 8
#define En 100000
#define Un 20000
#define Gn 20000
#define Rn 64
#define Dn 16
#define Cn 2
#define ND (Bn*Dn)   /* 1024 floats per node row */
#define NPB 8        /* agg rows per block in k_xf2 */

// Scratch (device globals: allocation-free rule)
__device__ float g_h[(size_t)Nn * ND];     // ~204.8 MB, [node][b][d], updated in place
__device__ float g_agg[(size_t)Un * ND];   // ~81.9 MB, per-layer edge sums (reused)
__device__ int   g_csr[Ln * En];
__device__ int   g_off[Ln * (Un + 1)];
__device__ int   g_cnt[Ln * Un];
__device__ int   g_cur[Ln * Un];

__global__ void k_zero_h() {
    size_t i = (size_t)blockIdx.x * blockDim.x + threadIdx.x;
    size_t n4 = (size_t)Nn * ND / 4;
    if (i < n4) ((float4*)g_h)[i] = make_float4(0.f, 0.f, 0.f, 0.f);
}

__global__ void k_zero_int() {
    int i = blockIdx.x * blockDim.x + threadIdx.x;
    if (i < Ln * Un) { g_cnt[i] = 0; g_cur[i] = 0; }
}

// h[gene_map[g]] = X[b,g] * w_in + b_in  (block = gene, thread = (b, j0))
__global__ void k_gene(const float* __restrict__ X, const float* __restrict__ w_in,
                       const float* __restrict__ b_in, const int* __restrict__ gene_map) {
    int g = blockIdx.x;
    int t = threadIdx.x;
    int b = t >> 2, j0 = (t & 3) << 2;
    int node = gene_map[g];
    float x = X[(size_t)b * Gn + g];
    float4 w  = *(const float4*)(w_in + j0);
    float4 bi = *(const float4*)(b_in + j0);
    float4 v = make_float4(fmaf(x, w.x, bi.x), fmaf(x, w.y, bi.y),
                           fmaf(x, w.z, bi.z), fmaf(x, w.w, bi.w));
    *(float4*)(g_h + (size_t)node * ND + t * 4) = v;
}

__global__ void k_hist(const int* __restrict__ dst_pos) {
    int i = blockIdx.x * blockDim.x + threadIdx.x;
    if (i < Ln * En) {
        int l = i / En;
        atomicAdd(&g_cnt[l * Un + dst_pos[i]], 1);
    }
}

// Exclusive scan of counts -> offsets, one block per layer.
__global__ void k_scan() {
    int l = blockIdx.x;
    const int* c = g_cnt + l * Un;
    int* o = g_off + l * (Un + 1);
    __shared__ int sh[1024];
    __shared__ int sbase;
    if (threadIdx.x == 0) sbase = 0;
    __syncthreads();
    for (int start = 0; start < Un; start += 1024) {
        int idx = start + (int)threadIdx.x;
        int v = (idx < Un) ? c[idx] : 0;
        sh[threadIdx.x] = v;
        __syncthreads();
        for (int st = 1; st < 1024; st <<= 1) {
            int tv = (threadIdx.x >= (unsigned)st) ? sh[threadIdx.x - st] : 0;
            __syncthreads();
            sh[threadIdx.x] += tv;
            __syncthreads();
        }
        if (idx < Un) o[idx] = sbase + sh[threadIdx.x] - v;  // exclusive
        __syncthreads();
        if (threadIdx.x == 0) sbase += sh[1023];
        __syncthreads();
    }
    if (threadIdx.x == 0) o[Un] = sbase;
}

__global__ void k_fill(const int* __restrict__ dst_pos) {
    int i = blockIdx.x * blockDim.x + threadIdx.x;
    if (i < Ln * En) {
        int l = i / En;
        int e = i - l * En;
        int u = dst_pos[i];
        int slot = g_off[l * (Un + 1) + u] + atomicAdd(&g_cur[l * Un + u], 1);
        g_csr[l * En + slot] = e;
    }
}

// Sort each bucket by edge id (deterministic sum order), then map edge id -> src node id.
__global__ void k_sortconv(const int* __restrict__ src) {
    int gid = blockIdx.x * blockDim.x + threadIdx.x;
    if (gid >= Ln * Un) return;
    int l = gid / Un;
    int u = gid - l * Un;
    int* seg = g_csr + l * En;
    int lo = g_off[l * (Un + 1) + u];
    int hi = g_off[l * (Un + 1) + u + 1];
    for (int i = lo + 1; i < hi; i++) {
        int key = seg[i];
        int j = i - 1;
        while (j >= lo && seg[j] > key) { seg[j + 1] = seg[j]; j--; }
        seg[j + 1] = key;
    }
    const int* sl = src + l * En;
    for (int i = lo; i < hi; i++) seg[i] = sl[seg[i]];
}

// Pure edge-sum: agg[u][quarter] = sum_edges h[src][quarter].
// Block = (u, quarter); 64 threads cover 256 floats (quarter of a row).
// Quarter phase footprint: 51MB h + 20MB agg -> L2-resident, repeats + agg stay in L2.
__global__ __launch_bounds__(64) void k_gsum(int l) {
    int u = blockIdx.x;
    int tt = threadIdx.x;
    size_t col = ((size_t)blockIdx.y << 8) + (tt << 2);

    const int* off = g_off + l * (Un + 1);
    int lo = off[u], hi = off[u + 1];
    int n = hi - lo;
    const int* e = g_csr + l * En + lo;

    float4 acc = make_float4(0.f, 0.f, 0.f, 0.f);
    float4 p0, p1;
    if (n > 0) p0 = *(const float4*)(g_h + (size_t)e[0] * ND + col);
    if (n > 1) p1 = *(const float4*)(g_h + (size_t)e[1] * ND + col);
    for (int i = 0; i < n; i++) {
        float4 v = p0;
        p0 = p1;
        if (i + 2 < n) p1 = *(const float4*)(g_h + (size_t)e[i + 2] * ND + col);
        acc.x += v.x; acc.y += v.y; acc.z += v.z; acc.w += v.w;
    }
    // normal store: agg quarter stays L2-resident for k_xf2's read
    *(float4*)(g_agg + (size_t)u * ND + col) = acc;
}

// Streaming transform of the 20K agg rows: h[dstu[u]] = tanh(agg[u] @ W + bias[dstu[u]]).
// Block handles NPB consecutive agg rows; thread = (b, q); W in registers.
// agg read with __ldcs (last consumer -> evict-first, frees L2 for next phase).
__global__ __launch_bounds__(256, 2) void k_xf2(int l, const float* __restrict__ W,
                                                const float* __restrict__ bias,
                                                const int* __restrict__ dstu) {
    const float* Wl = W + l * Dn * Dn;
    int t = threadIdx.x;
    int b = t >> 2, q = t & 3;
    int j0 = q << 2;
    int u0 = blockIdx.x * NPB;

    // W[k][j0..j0+3] as two packed f32x2 pairs per k, in registers.
    unsigned long long w01[16], w23[16];
    #pragma unroll
    for (int k = 0; k < 16; k++) {
        ulonglong2 wp = *(const ulonglong2*)(Wl + k * Dn + j0);
        w01[k] = wp.x;
        w23[k] = wp.y;
    }

    const float4* ap = (const float4*)(g_agg + (size_t)u0 * ND + (b << 4));
    float4 c0 = __ldcs(ap + 0), c1 = __ldcs(ap + 1), c2 = __ldcs(ap + 2), c3 = __ldcs(ap + 3);

    #pragma unroll
    for (int nn = 0; nn < NPB; nn++) {
        float4 v0 = c0, v1 = c1, v2 = c2, v3 = c3;
        if (nn + 1 < NPB) {
            const float4* np = (const float4*)(g_agg + (size_t)(u0 + nn + 1) * ND + (b << 4));
            c0 = __ldcs(np + 0); c1 = __ldcs(np + 1); c2 = __ldcs(np + 2); c3 = __ldcs(np + 3);
        }
        unsigned long long acc01 = 0ull, acc23 = 0ull;
        #define XF_STEP(kk, hval) { unsigned long long hk2_; \
            asm("mov.b64 %0, {%1, %1};" : "=l"(hk2_) : "f"(hval)); \
            asm("fma.rn.f32x2 %0, %1, %2, %0;" : "+l"(acc01) : "l"(hk2_), "l"(w01[kk])); \
            asm("fma.rn.f32x2 %0, %1, %2, %0;" : "+l"(acc23) : "l"(hk2_), "l"(w23[kk])); }
        XF_STEP(0,  v0.x) XF_STEP(1,  v0.y) XF_STEP(2,  v0.z) XF_STEP(3,  v0.w)
        XF_STEP(4,  v1.x) XF_STEP(5,  v1.y) XF_STEP(6,  v1.z) XF_STEP(7,  v1.w)
        XF_STEP(8,  v2.x) XF_STEP(9,  v2.y) XF_STEP(10, v2.z) XF_STEP(11, v2.w)
        XF_STEP(12, v3.x) XF_STEP(13, v3.y) XF_STEP(14, v3.z) XF_STEP(15, v3.w)
        #undef XF_STEP

        int node = dstu[u0 + nn];
        float4 bi = *(const float4*)(bias + (size_t)node * Dn + j0);
        float r0, r1, r2, r3;
        asm("mov.b64 {%0, %1}, %2;" : "=f"(r0), "=f"(r1) : "l"(acc01));
        asm("mov.b64 {%0, %1}, %2;" : "=f"(r2), "=f"(r3) : "l"(acc23));
        float4 outv = make_float4(tanhf(r0 + bi.x), tanhf(r1 + bi.y),
                                  tanhf(r2 + bi.z), tanhf(r3 + bi.w));
        *(float4*)(g_h + (size_t)node * ND + t * 4) = outv;
    }
}

// out[b,c] = sum_{r,j} h[root[r]][b][j] * W_head[c][r*16+j] + b_head[c]
__global__ void k_head(const int* __restrict__ roots, const float* __restrict__ Wh,
                       const float* __restrict__ bh, float* __restrict__ out) {
    int b = blockIdx.x;
    int t = threadIdx.x;
    float a0 = 0.f, a1 = 0.f;
    for (int i = t; i < Rn * Dn; i += 256) {
        int r = i >> 4, j = i & 15;
        float f = g_h[(size_t)roots[r] * ND + (b << 4) + j];
        a0 = fmaf(f, Wh[i], a0);
        a1 = fmaf(f, Wh[Rn * Dn + i], a1);
    }
    __shared__ float s0[256], s1[256];
    s0[t] = a0; s1[t] = a1;
    __syncthreads();
    for (int st = 128; st > 0; st >>= 1) {
        if (t < st) { s0[t] += s0[t + st]; s1[t] += s1[t + st]; }
        __syncthreads();
    }
    if (t == 0) {
        out[b * Cn + 0] = s0[0] + bh[0];
        out[b * Cn + 1] = s1[0] + bh[1];
    }
}

extern "C" void kernel_launch(void* const* d_in, const int* in_sizes, int n_in,
                              void* d_out, int out_size) {
    (void)in_sizes; (void)n_in; (void)out_size;
    const float* X          = (const float*)d_in[0];
    const float* w_in       = (const float*)d_in[1];
    const float* b_in       = (const float*)d_in[2];
    const float* W          = (const float*)d_in[3];
    const float* bias       = (const float*)d_in[4];
    const float* W_head     = (const float*)d_in[5];
    const float* b_head     = (const float*)d_in[6];
    const int*   gene_map   = (const int*)d_in[7];
    const int*   src        = (const int*)d_in[8];
    const int*   dst_pos    = (const int*)d_in[9];
    const int*   dst_unique = (const int*)d_in[10];
    const int*   root_ids   = (const int*)d_in[11];
    float* out = (float*)d_out;

    {
        size_t n4 = (size_t)Nn * ND / 4;
        k_zero_h<<<(unsigned)((n4 + 255) / 256), 256>>>();
    }
    k_zero_int<<<(Ln * Un + 255) / 256, 256>>>();
    k_gene<<<Gn, 256>>>(X, w_in, b_in, gene_map);

    // Batched CSR build for all 8 layers (depends only on dst_pos / src)
    k_hist<<<(Ln * En + 255) / 256, 256>>>(dst_pos);
    k_scan<<<Ln, 1024>>>();
    k_fill<<<(Ln * En + 255) / 256, 256>>>(dst_pos);
    k_sortconv<<<(Ln * Un + 255) / 256, 256>>>(src);

    for (int l = 0; l < Ln; l++) {
        k_gsum<<<dim3(Un, 4), 64>>>(l);                        // sum raw h rows (B-quartered for L2)
        k_xf2<<<Un / NPB, 256>>>(l, W, bias, dst_unique + l * Un);  // transform 20K rows + scatter
    }

    k_head<<<Bn, 256>>>(root_ids, W_head, b_head, out);
}

// round 9
// speedup vs baseline: 2.0003x; 1.0335x over previous
#include <cuda_runtime.h>
#include <cstdint>

#define Bn 64
#define Nn 50000
#define Ln 8
#define En 100000
#define Un 20000
#define Gn 20000
#define Rn 64
#define Dn 16
#define Cn 2
#define ND (Bn*Dn)   /* 1024 floats per node row */
#define NPB 8        /* agg rows per block in k_xf2 */

// Scratch (device globals: allocation-free rule).
// g_h is zero at module load; rows never written by gene/xf2 stay zero forever
// (reads of such rows only happen for root nodes in k_head, where 0 is correct).
__device__ float g_h[(size_t)Nn * ND];     // ~204.8 MB, [node][b][d], updated in place
__device__ float g_agg[(size_t)Un * ND];   // ~81.9 MB, per-layer edge sums (reused)
__device__ int   g_csr[Ln * En];
__device__ int   g_off[Ln * (Un + 1)];
__device__ int   g_len[Ln * Un];           // post-prune bucket lengths
__device__ int   g_cnt[Ln * Un];
__device__ int   g_cur[Ln * Un];
__device__ int   g_alive[Nn];              // node has a nonzero row yet?

__global__ void k_zero_int() {
    int i = blockIdx.x * blockDim.x + threadIdx.x;
    if (i < Ln * Un) { g_cnt[i] = 0; g_cur[i] = 0; }
    if (i < Nn) g_alive[i] = 0;
}

// h[gene_map[g]] = X[b,g] * w_in + b_in  (block = gene, thread = (b, j0))
__global__ void k_gene(const float* __restrict__ X, const float* __restrict__ w_in,
                       const float* __restrict__ b_in, const int* __restrict__ gene_map) {
    int g = blockIdx.x;
    int t = threadIdx.x;
    int b = t >> 2, j0 = (t & 3) << 2;
    int node = gene_map[g];
    if (t == 0) g_alive[node] = 1;
    float x = X[(size_t)b * Gn + g];
    float4 w  = *(const float4*)(w_in + j0);
    float4 bi = *(const float4*)(b_in + j0);
    float4 v = make_float4(fmaf(x, w.x, bi.x), fmaf(x, w.y, bi.y),
                           fmaf(x, w.z, bi.z), fmaf(x, w.w, bi.w));
    *(float4*)(g_h + (size_t)node * ND + t * 4) = v;
}

__global__ void k_hist(const int* __restrict__ dst_pos) {
    int i = blockIdx.x * blockDim.x + threadIdx.x;
    if (i < Ln * En) {
        int l = i / En;
        atomicAdd(&g_cnt[l * Un + dst_pos[i]], 1);
    }
}

// Exclusive scan of counts -> offsets. Block per layer; 20 counts per thread,
// one 1024-wide block scan (single pass).
__global__ void k_scan() {
    int l = blockIdx.x;
    const int* c = g_cnt + l * Un;
    int* o = g_off + l * (Un + 1);
    int t = threadIdx.x;
    int base = t * 20;
    int s = 0;
    #pragma unroll
    for (int i = 0; i < 20; i++) {
        int idx = base + i;
        s += (idx < Un) ? c[idx] : 0;
    }
    __shared__ int sh[1024];
    sh[t] = s;
    __syncthreads();
    for (int st = 1; st < 1024; st <<= 1) {
        int v = (t >= st) ? sh[t - st] : 0;
        __syncthreads();
        sh[t] += v;
        __syncthreads();
    }
    int run = (t > 0) ? sh[t - 1] : 0;   // exclusive prefix of this thread's chunk
    #pragma unroll
    for (int i = 0; i < 20; i++) {
        int idx = base + i;
        if (idx < Un) {
            o[idx] = run;
            run += c[idx];
        }
    }
    if (t == 1023) o[Un] = sh[1023];
}

__global__ void k_fill(const int* __restrict__ dst_pos) {
    int i = blockIdx.x * blockDim.x + threadIdx.x;
    if (i < Ln * En) {
        int l = i / En;
        int e = i - l * En;
        int u = dst_pos[i];
        int slot = g_off[l * (Un + 1) + u] + atomicAdd(&g_cur[l * Un + u], 1);
        g_csr[l * En + slot] = e;
    }
}

// Sort each bucket by edge id (deterministic sum order), then map edge id -> src node id.
__global__ void k_sortconv(const int* __restrict__ src) {
    int gid = blockIdx.x * blockDim.x + threadIdx.x;
    if (gid >= Ln * Un) return;
    int l = gid / Un;
    int u = gid - l * Un;
    int* seg = g_csr + l * En;
    int lo = g_off[l * (Un + 1) + u];
    int hi = g_off[l * (Un + 1) + u + 1];
    for (int i = lo + 1; i < hi; i++) {
        int key = seg[i];
        int j = i - 1;
        while (j >= lo && seg[j] > key) { seg[j + 1] = seg[j]; j--; }
        seg[j + 1] = key;
    }
    const int* sl = src + l * En;
    for (int i = lo; i < hi; i++) seg[i] = sl[seg[i]];
}

// Stable in-place compaction of layer-l buckets to alive srcs (dead rows are
// exactly zero -> dropping them is bit-exact). Uses pre-layer-l alive set.
__global__ void k_prune(int l) {
    int u = blockIdx.x * blockDim.x + threadIdx.x;
    if (u >= Un) return;
    int* seg = g_csr + l * En;
    int lo = g_off[l * (Un + 1) + u];
    int hi = g_off[l * (Un + 1) + u + 1];
    int w = lo;
    for (int i = lo; i < hi; i++) {
        int s = seg[i];
        if (g_alive[s]) seg[w++] = s;
    }
    g_len[l * Un + u] = w - lo;
}

// After layer l's (virtual) update, dst nodes have nonzero rows.
__global__ void k_mark(int l, const int* __restrict__ dstu) {
    int u = blockIdx.x * blockDim.x + threadIdx.x;
    if (u < Un) g_alive[dstu[u]] = 1;
}

// Pure edge-sum: agg[u][quarter] = sum_(alive edges) h[src][quarter].
// Block = (u, quarter); 64 threads cover 256 floats (quarter of a row).
__global__ __launch_bounds__(64) void k_gsum(int l) {
    int u = blockIdx.x;
    int tt = threadIdx.x;
    size_t col = ((size_t)blockIdx.y << 8) + (tt << 2);

    int lo = g_off[l * (Un + 1) + u];
    int n = g_len[l * Un + u];
    const int* e = g_csr + l * En + lo;

    float4 acc = make_float4(0.f, 0.f, 0.f, 0.f);
    float4 p0, p1;
    if (n > 0) p0 = *(const float4*)(g_h + (size_t)e[0] * ND + col);
    if (n > 1) p1 = *(const float4*)(g_h + (size_t)e[1] * ND + col);
    for (int i = 0; i < n; i++) {
        float4 v = p0;
        p0 = p1;
        if (i + 2 < n) p1 = *(const float4*)(g_h + (size_t)e[i + 2] * ND + col);
        acc.x += v.x; acc.y += v.y; acc.z += v.z; acc.w += v.w;
    }
    *(float4*)(g_agg + (size_t)u * ND + col) = acc;
}

// Streaming transform of the 20K agg rows: h[dstu[u]] = tanh(agg[u] @ W + bias[dstu[u]]).
// Block handles NPB consecutive agg rows; thread = (b, q); W in registers.
__global__ __launch_bounds__(256, 2) void k_xf2(int l, const float* __restrict__ W,
                                                const float* __restrict__ bias,
                                                const int* __restrict__ dstu) {
    const float* Wl = W + l * Dn * Dn;
    int t = threadIdx.x;
    int b = t >> 2, q = t & 3;
    int j0 = q << 2;
    int u0 = blockIdx.x * NPB;

    unsigned long long w01[16], w23[16];
    #pragma unroll
    for (int k = 0; k < 16; k++) {
        ulonglong2 wp = *(const ulonglong2*)(Wl + k * Dn + j0);
        w01[k] = wp.x;
        w23[k] = wp.y;
    }

    const float4* ap = (const float4*)(g_agg + (size_t)u0 * ND + (b << 4));
    float4 c0 = __ldcs(ap + 0), c1 = __ldcs(ap + 1), c2 = __ldcs(ap + 2), c3 = __ldcs(ap + 3);

    #pragma unroll
    for (int nn = 0; nn < NPB; nn++) {
        float4 v0 = c0, v1 = c1, v2 = c2, v3 = c3;
        if (nn + 1 < NPB) {
            const float4* np = (const float4*)(g_agg + (size_t)(u0 + nn + 1) * ND + (b << 4));
            c0 = __ldcs(np + 0); c1 = __ldcs(np + 1); c2 = __ldcs(np + 2); c3 = __ldcs(np + 3);
        }
        unsigned long long acc01 = 0ull, acc23 = 0ull;
        #define XF_STEP(kk, hval) { unsigned long long hk2_; \
            asm("mov.b64 %0, {%1, %1};" : "=l"(hk2_) : "f"(hval)); \
            asm("fma.rn.f32x2 %0, %1, %2, %0;" : "+l"(acc01) : "l"(hk2_), "l"(w01[kk])); \
            asm("fma.rn.f32x2 %0, %1, %2, %0;" : "+l"(acc23) : "l"(hk2_), "l"(w23[kk])); }
        XF_STEP(0,  v0.x) XF_STEP(1,  v0.y) XF_STEP(2,  v0.z) XF_STEP(3,  v0.w)
        XF_STEP(4,  v1.x) XF_STEP(5,  v1.y) XF_STEP(6,  v1.z) XF_STEP(7,  v1.w)
        XF_STEP(8,  v2.x) XF_STEP(9,  v2.y) XF_STEP(10, v2.z) XF_STEP(11, v2.w)
        XF_STEP(12, v3.x) XF_STEP(13, v3.y) XF_STEP(14, v3.z) XF_STEP(15, v3.w)
        #undef XF_STEP

        int node = dstu[u0 + nn];
        float4 bi = *(const float4*)(bias + (size_t)node * Dn + j0);
        float r0, r1, r2, r3;
        asm("mov.b64 {%0, %1}, %2;" : "=f"(r0), "=f"(r1) : "l"(acc01));
        asm("mov.b64 {%0, %1}, %2;" : "=f"(r2), "=f"(r3) : "l"(acc23));
        float4 outv = make_float4(tanhf(r0 + bi.x), tanhf(r1 + bi.y),
                                  tanhf(r2 + bi.z), tanhf(r3 + bi.w));
        *(float4*)(g_h + (size_t)node * ND + t * 4) = outv;
    }
}

// out[b,c] = sum_{r,j} h[root[r]][b][j] * W_head[c][r*16+j] + b_head[c]
__global__ void k_head(const int* __restrict__ roots, const float* __restrict__ Wh,
                       const float* __restrict__ bh, float* __restrict__ out) {
    int b = blockIdx.x;
    int t = threadIdx.x;
    float a0 = 0.f, a1 = 0.f;
    for (int i = t; i < Rn * Dn; i += 256) {
        int r = i >> 4, j = i & 15;
        float f = g_h[(size_t)roots[r] * ND + (b << 4) + j];
        a0 = fmaf(f, Wh[i], a0);
        a1 = fmaf(f, Wh[Rn * Dn + i], a1);
    }
    __shared__ float s0[256], s1[256];
    s0[t] = a0; s1[t] = a1;
    __syncthreads();
    for (int st = 128; st > 0; st >>= 1) {
        if (t < st) { s0[t] += s0[t + st]; s1[t] += s1[t + st]; }
        __syncthreads();
    }
    if (t == 0) {
        out[b * Cn + 0] = s0[0] + bh[0];
        out[b * Cn + 1] = s1[0] + bh[1];
    }
}

extern "C" void kernel_launch(void* const* d_in, const int* in_sizes, int n_in,
                              void* d_out, int out_size) {
    (void)in_sizes; (void)n_in; (void)out_size;
    const float* X          = (const float*)d_in[0];
    const float* w_in       = (const float*)d_in[1];
    const float* b_in       = (const float*)d_in[2];
    const float* W          = (const float*)d_in[3];
    const float* bias       = (const float*)d_in[4];
    const float* W_head     = (const float*)d_in[5];
    const float* b_head     = (const float*)d_in[6];
    const int*   gene_map   = (const int*)d_in[7];
    const int*   src        = (const int*)d_in[8];
    const int*   dst_pos    = (const int*)d_in[9];
    const int*   dst_unique = (const int*)d_in[10];
    const int*   root_ids   = (const int*)d_in[11];
    float* out = (float*)d_out;

    k_zero_int<<<(Ln * Un + 255) / 256, 256>>>();
    k_gene<<<Gn, 256>>>(X, w_in, b_in, gene_map);

    // Batched CSR build for all 8 layers (depends only on dst_pos / src)
    k_hist<<<(Ln * En + 255) / 256, 256>>>(dst_pos);
    k_scan<<<Ln, 1024>>>();
    k_fill<<<(Ln * En + 255) / 256, 256>>>(dst_pos);
    k_sortconv<<<(Ln * Un + 255) / 256, 256>>>(src);

    // Dead-edge pruning: layer l keeps only srcs alive before layer l.
    for (int l = 0; l < Ln; l++) {
        k_prune<<<(Un + 255) / 256, 256>>>(l);
        k_mark<<<(Un + 255) / 256, 256>>>(l, dst_unique + l * Un);
    }

    for (int l = 0; l < Ln; l++) {
        k_gsum<<<dim3(Un, 4), 64>>>(l);                        // sum alive h rows (B-quartered for L2)
        k_xf2<<<Un / NPB, 256>>>(l, W, bias, dst_unique + l * Un);  // transform 20K rows + scatter
    }

    k_head<<<Bn, 256>>>(root_ids, W_head, b_head, out);
}

// round 10
// speedup vs baseline: 2.6944x; 1.3470x over previous
#include <cuda_runtime.h>
#include <cuda_fp16.h>
#include <cstdint>

#define Bn 64
#define Nn 50000
#define Ln 8
#define En 100000
#define Un 20000
#define Gn 20000
#define Rn 64
#define Dn 16
#define Cn 2
#define ND (Bn*Dn)   /* 1024 elements per node row */
#define NPB 8        /* agg rows per block in k_xf2 */

// Scratch (device globals: allocation-free rule).
// g_h is fp16 (half traffic on the dominant gather stream); zero at module load.
__device__ __half g_h[(size_t)Nn * ND];    // ~102.4 MB, [node][b][d], updated in place
__device__ float  g_agg[(size_t)Un * ND];  // ~81.9 MB fp32 edge sums (accumulation precision)
__device__ int    g_csr[Ln * En];
__device__ int    g_off[Ln * (Un + 1)];
__device__ int    g_len[Ln * Un];          // post-prune bucket lengths
__device__ int    g_cnt[Ln * Un];
__device__ int    g_cur[Ln * Un];
__device__ int    g_alive[Nn];             // node has a nonzero row yet?

__global__ void k_zero_int() {
    int i = blockIdx.x * blockDim.x + threadIdx.x;
    if (i < Ln * Un) { g_cnt[i] = 0; g_cur[i] = 0; }
    if (i < Nn) g_alive[i] = 0;
}

// h[gene_map[g]] = fp16( X[b,g] * w_in + b_in )  (block = gene, thread = (b, j0))
__global__ void k_gene(const float* __restrict__ X, const float* __restrict__ w_in,
                       const float* __restrict__ b_in, const int* __restrict__ gene_map) {
    int g = blockIdx.x;
    int t = threadIdx.x;
    int b = t >> 2, j0 = (t & 3) << 2;
    int node = gene_map[g];
    if (t == 0) g_alive[node] = 1;
    float x = X[(size_t)b * Gn + g];
    float4 w  = *(const float4*)(w_in + j0);
    float4 bi = *(const float4*)(b_in + j0);
    __half2 h01 = __floats2half2_rn(fmaf(x, w.x, bi.x), fmaf(x, w.y, bi.y));
    __half2 h23 = __floats2half2_rn(fmaf(x, w.z, bi.z), fmaf(x, w.w, bi.w));
    __half2* dst = (__half2*)(g_h + (size_t)node * ND + t * 4);
    dst[0] = h01;
    dst[1] = h23;
}

__global__ void k_hist(const int* __restrict__ dst_pos) {
    int i = blockIdx.x * blockDim.x + threadIdx.x;
    if (i < Ln * En) {
        int l = i / En;
        atomicAdd(&g_cnt[l * Un + dst_pos[i]], 1);
    }
}

// Exclusive scan of counts -> offsets. Block per layer; 20 counts per thread.
__global__ void k_scan() {
    int l = blockIdx.x;
    const int* c = g_cnt + l * Un;
    int* o = g_off + l * (Un + 1);
    int t = threadIdx.x;
    int base = t * 20;
    int s = 0;
    #pragma unroll
    for (int i = 0; i < 20; i++) {
        int idx = base + i;
        s += (idx < Un) ? c[idx] : 0;
    }
    __shared__ int sh[1024];
    sh[t] = s;
    __syncthreads();
    for (int st = 1; st < 1024; st <<= 1) {
        int v = (t >= st) ? sh[t - st] : 0;
        __syncthreads();
        sh[t] += v;
        __syncthreads();
    }
    int run = (t > 0) ? sh[t - 1] : 0;
    #pragma unroll
    for (int i = 0; i < 20; i++) {
        int idx = base + i;
        if (idx < Un) {
            o[idx] = run;
            run += c[idx];
        }
    }
    if (t == 1023) o[Un] = sh[1023];
}

__global__ void k_fill(const int* __restrict__ dst_pos) {
    int i = blockIdx.x * blockDim.x + threadIdx.x;
    if (i < Ln * En) {
        int l = i / En;
        int e = i - l * En;
        int u = dst_pos[i];
        int slot = g_off[l * (Un + 1) + u] + atomicAdd(&g_cur[l * Un + u], 1);
        g_csr[l * En + slot] = e;
    }
}

// Sort each bucket by edge id (deterministic sum order), then map edge id -> src node id.
__global__ void k_sortconv(const int* __restrict__ src) {
    int gid = blockIdx.x * blockDim.x + threadIdx.x;
    if (gid >= Ln * Un) return;
    int l = gid / Un;
    int u = gid - l * Un;
    int* seg = g_csr + l * En;
    int lo = g_off[l * (Un + 1) + u];
    int hi = g_off[l * (Un + 1) + u + 1];
    for (int i = lo + 1; i < hi; i++) {
        int key = seg[i];
        int j = i - 1;
        while (j >= lo && seg[j] > key) { seg[j + 1] = seg[j]; j--; }
        seg[j + 1] = key;
    }
    const int* sl = src + l * En;
    for (int i = lo; i < hi; i++) seg[i] = sl[seg[i]];
}

// Stable compaction to alive srcs (dead rows exactly zero -> bit-exact drop).
__global__ void k_prune(int l) {
    int u = blockIdx.x * blockDim.x + threadIdx.x;
    if (u >= Un) return;
    int* seg = g_csr + l * En;
    int lo = g_off[l * (Un + 1) + u];
    int hi = g_off[l * (Un + 1) + u + 1];
    int w = lo;
    for (int i = lo; i < hi; i++) {
        int s = seg[i];
        if (g_alive[s]) seg[w++] = s;
    }
    g_len[l * Un + u] = w - lo;
}

__global__ void k_mark(int l, const int* __restrict__ dstu) {
    int u = blockIdx.x * blockDim.x + threadIdx.x;
    if (u < Un) g_alive[dstu[u]] = 1;
}

// Edge-sum: agg[u][half] = sum_(alive edges) fp32(h[src][half]).
// Block = (u, half); 64 threads, each owns 8 consecutive elements (16B fp16 load).
// Phase footprint: 51MB fp16 h-half + agg -> L2-friendly.
__global__ __launch_bounds__(64) void k_gsum(int l) {
    int u = blockIdx.x;
    int tt = threadIdx.x;
    size_t col = ((size_t)blockIdx.y << 9) + (tt << 3);   // element offset (halfs)

    int lo = g_off[l * (Un + 1) + u];
    int n = g_len[l * Un + u];
    const int* e = g_csr + l * En + lo;

    float a0 = 0.f, a1 = 0.f, a2 = 0.f, a3 = 0.f;
    float a4 = 0.f, a5 = 0.f, a6 = 0.f, a7 = 0.f;
    uint4 p0, p1;
    if (n > 0) p0 = *(const uint4*)(g_h + (size_t)e[0] * ND + col);
    if (n > 1) p1 = *(const uint4*)(g_h + (size_t)e[1] * ND + col);
    for (int i = 0; i < n; i++) {
        uint4 d = p0;
        p0 = p1;
        if (i + 2 < n) p1 = *(const uint4*)(g_h + (size_t)e[i + 2] * ND + col);
        float2 f0 = __half22float2(*(__half2*)&d.x);
        float2 f1 = __half22float2(*((__half2*)&d.x + 1));
        float2 f2 = __half22float2(*(__half2*)&d.y);
        float2 f3 = __half22float2(*((__half2*)&d.y + 1));
        // uint4 fields: x,y,z,w each hold 2 halfs
        float2 g0 = __half22float2(*(__half2*)&d.z);
        float2 g1 = __half22float2(*((__half2*)&d.z + 1));
        float2 g2 = __half22float2(*(__half2*)&d.w);
        float2 g3 = __half22float2(*((__half2*)&d.w + 1));
        a0 += f0.x; a1 += f0.y; a2 += f2.x; a3 += f2.y;
        a4 += g0.x; a5 += g0.y; a6 += g2.x; a7 += g2.y;
        // note: f1,f3,g1,g3 alias the same data lanes; recompute cleanly below
        (void)f1; (void)f3; (void)g1; (void)g3;
    }
    // The unpack above must cover all 8 halfs exactly once: redo mapping explicitly.
    // (x: h0 h1) (y: h2 h3) (z: h4 h5) (w: h6 h7)
    // a0..a7 correspond to h0..h7 — fix: recompute is impossible post-loop, so the
    // loop body above already assigned: a0,a1 <- x; a2,a3 <- y; a4,a5 <- z; a6,a7 <- w.
    float* ar = (float*)&a0;  (void)ar;

    float4 o0 = make_float4(a0, a1, a2, a3);
    float4 o1 = make_float4(a4, a5, a6, a7);
    float* dst = g_agg + (size_t)u * ND + col;
    *(float4*)dst = o0;
    *(float4*)(dst + 4) = o1;
}

// Streaming transform of the 20K agg rows: h[dstu[u]] = fp16(tanh(agg[u] @ W + bias)).
__global__ __launch_bounds__(256, 2) void k_xf2(int l, const float* __restrict__ W,
                                                const float* __restrict__ bias,
                                                const int* __restrict__ dstu) {
    const float* Wl = W + l * Dn * Dn;
    int t = threadIdx.x;
    int b = t >> 2, q = t & 3;
    int j0 = q << 2;
    int u0 = blockIdx.x * NPB;

    unsigned long long w01[16], w23[16];
    #pragma unroll
    for (int k = 0; k < 16; k++) {
        ulonglong2 wp = *(const ulonglong2*)(Wl + k * Dn + j0);
        w01[k] = wp.x;
        w23[k] = wp.y;
    }

    const float4* ap = (const float4*)(g_agg + (size_t)u0 * ND + (b << 4));
    float4 c0 = __ldcs(ap + 0), c1 = __ldcs(ap + 1), c2 = __ldcs(ap + 2), c3 = __ldcs(ap + 3);

    #pragma unroll
    for (int nn = 0; nn < NPB; nn++) {
        float4 v0 = c0, v1 = c1, v2 = c2, v3 = c3;
        if (nn + 1 < NPB) {
            const float4* np = (const float4*)(g_agg + (size_t)(u0 + nn + 1) * ND + (b << 4));
            c0 = __ldcs(np + 0); c1 = __ldcs(np + 1); c2 = __ldcs(np + 2); c3 = __ldcs(np + 3);
        }
        unsigned long long acc01 = 0ull, acc23 = 0ull;
        #define XF_STEP(kk, hval) { unsigned long long hk2_; \
            asm("mov.b64 %0, {%1, %1};" : "=l"(hk2_) : "f"(hval)); \
            asm("fma.rn.f32x2 %0, %1, %2, %0;" : "+l"(acc01) : "l"(hk2_), "l"(w01[kk])); \
            asm("fma.rn.f32x2 %0, %1, %2, %0;" : "+l"(acc23) : "l"(hk2_), "l"(w23[kk])); }
        XF_STEP(0,  v0.x) XF_STEP(1,  v0.y) XF_STEP(2,  v0.z) XF_STEP(3,  v0.w)
        XF_STEP(4,  v1.x) XF_STEP(5,  v1.y) XF_STEP(6,  v1.z) XF_STEP(7,  v1.w)
        XF_STEP(8,  v2.x) XF_STEP(9,  v2.y) XF_STEP(10, v2.z) XF_STEP(11, v2.w)
        XF_STEP(12, v3.x) XF_STEP(13, v3.y) XF_STEP(14, v3.z) XF_STEP(15, v3.w)
        #undef XF_STEP

        int node = dstu[u0 + nn];
        float4 bi = *(const float4*)(bias + (size_t)node * Dn + j0);
        float r0, r1, r2, r3;
        asm("mov.b64 {%0, %1}, %2;" : "=f"(r0), "=f"(r1) : "l"(acc01));
        asm("mov.b64 {%0, %1}, %2;" : "=f"(r2), "=f"(r3) : "l"(acc23));
        __half2 o01 = __floats2half2_rn(tanhf(r0 + bi.x), tanhf(r1 + bi.y));
        __half2 o23 = __floats2half2_rn(tanhf(r2 + bi.z), tanhf(r3 + bi.w));
        __half2* dst = (__half2*)(g_h + (size_t)node * ND + t * 4);
        dst[0] = o01;
        dst[1] = o23;
    }
}

// out[b,c] = sum_{r,j} h[root[r]][b][j] * W_head[c][r*16+j] + b_head[c]
__global__ void k_head(const int* __restrict__ roots, const float* __restrict__ Wh,
                       const float* __restrict__ bh, float* __restrict__ out) {
    int b = blockIdx.x;
    int t = threadIdx.x;
    float a0 = 0.f, a1 = 0.f;
    for (int i = t; i < Rn * Dn; i += 256) {
        int r = i >> 4, j = i & 15;
        float f = __half2float(g_h[(size_t)roots[r] * ND + (b << 4) + j]);
        a0 = fmaf(f, Wh[i], a0);
        a1 = fmaf(f, Wh[Rn * Dn + i], a1);
    }
    __shared__ float s0[256], s1[256];
    s0[t] = a0; s1[t] = a1;
    __syncthreads();
    for (int st = 128; st > 0; st >>= 1) {
        if (t < st) { s0[t] += s0[t + st]; s1[t] += s1[t + st]; }
        __syncthreads();
    }
    if (t == 0) {
        out[b * Cn + 0] = s0[0] + bh[0];
        out[b * Cn + 1] = s1[0] + bh[1];
    }
}

extern "C" void kernel_launch(void* const* d_in, const int* in_sizes, int n_in,
                              void* d_out, int out_size) {
    (void)in_sizes; (void)n_in; (void)out_size;
    const float* X          = (const float*)d_in[0];
    const float* w_in       = (const float*)d_in[1];
    const float* b_in       = (const float*)d_in[2];
    const float* W          = (const float*)d_in[3];
    const float* bias       = (const float*)d_in[4];
    const float* W_head     = (const float*)d_in[5];
    const float* b_head     = (const float*)d_in[6];
    const int*   gene_map   = (const int*)d_in[7];
    const int*   src        = (const int*)d_in[8];
    const int*   dst_pos    = (const int*)d_in[9];
    const int*   dst_unique = (const int*)d_in[10];
    const int*   root_ids   = (const int*)d_in[11];
    float* out = (float*)d_out;

    k_zero_int<<<(Ln * Un + 255) / 256, 256>>>();
    k_gene<<<Gn, 256>>>(X, w_in, b_in, gene_map);

    // Batched CSR build for all 8 layers (depends only on dst_pos / src)
    k_hist<<<(Ln * En + 255) / 256, 256>>>(dst_pos);
    k_scan<<<Ln, 1024>>>();
    k_fill<<<(Ln * En + 255) / 256, 256>>>(dst_pos);
    k_sortconv<<<(Ln * Un + 255) / 256, 256>>>(src);

    // Dead-edge pruning: layer l keeps only srcs alive before layer l.
    for (int l = 0; l < Ln; l++) {
        k_prune<<<(Un + 255) / 256, 256>>>(l);
        k_mark<<<(Un + 255) / 256, 256>>>(l, dst_unique + l * Un);
    }

    for (int l = 0; l < Ln; l++) {
        k_gsum<<<dim3(Un, 2), 64>>>(l);                        // fp16 gather, fp32 accumulate
        k_xf2<<<Un / NPB, 256>>>(l, W, bias, dst_unique + l * Un);
    }

    k_head<<<Bn, 256>>>(root_ids, W_head, b_head, out);
}

// round 11
// speedup vs baseline: 2.8168x; 1.0454x over previous
#include <cuda_runtime.h>
#include <cuda_fp16.h>
#include <cstdint>

#define Bn 64
#define Nn 50000
#define Ln 8
#define En 100000
#define Un 20000
#define Gn 20000
#define Rn 64
#define Dn 16
#define Cn 2
#define ND (Bn*Dn)   /* 1024 elements per node row */
#define NPB 8        /* agg rows per block in k_xf2 */

// Scratch (device globals: allocation-free rule).
// g_h is fp16 (half traffic on the dominant gather stream); zero at module load.
__device__ __half g_h[(size_t)Nn * ND];    // ~102.4 MB, [node][b][d], updated in place
__device__ float  g_agg[(size_t)Un * ND];  // ~81.9 MB fp32 edge sums (accumulation precision)
__device__ int    g_csr[Ln * En];
__device__ int    g_off[Ln * (Un + 1)];
__device__ int    g_len[Ln * Un];          // post-prune bucket lengths
__device__ int    g_cnt[Ln * Un];
__device__ int    g_cur[Ln * Un];
__device__ int    g_first[Nn];             // first layer after which node is nonzero (-1 = gene)

__global__ void k_zero_int() {
    int i = blockIdx.x * blockDim.x + threadIdx.x;
    if (i < Ln * Un) { g_cnt[i] = 0; g_cur[i] = 0; }
    if (i < Nn) g_first[i] = 127;          // INF
}

// Mark aliveness: gene nodes alive from the start (-1); dst nodes alive after their layer.
__global__ void k_alive(const int* __restrict__ gene_map, const int* __restrict__ dst_unique) {
    int i = blockIdx.x * blockDim.x + threadIdx.x;
    if (i < Gn) {
        atomicMin(&g_first[gene_map[i]], -1);
    } else if (i < Gn + Ln * Un) {
        int k = i - Gn;
        atomicMin(&g_first[dst_unique[k]], k / Un);
    }
}

// h[gene_map[g]] = fp16( X[b,g] * w_in + b_in )  (block = gene, thread = (b, j0))
__global__ void k_gene(const float* __restrict__ X, const float* __restrict__ w_in,
                       const float* __restrict__ b_in, const int* __restrict__ gene_map) {
    int g = blockIdx.x;
    int t = threadIdx.x;
    int b = t >> 2, j0 = (t & 3) << 2;
    int node = gene_map[g];
    float x = X[(size_t)b * Gn + g];
    float4 w  = *(const float4*)(w_in + j0);
    float4 bi = *(const float4*)(b_in + j0);
    __half2 h01 = __floats2half2_rn(fmaf(x, w.x, bi.x), fmaf(x, w.y, bi.y));
    __half2 h23 = __floats2half2_rn(fmaf(x, w.z, bi.z), fmaf(x, w.w, bi.w));
    __half2* dst = (__half2*)(g_h + (size_t)node * ND + t * 4);
    dst[0] = h01;
    dst[1] = h23;
}

__global__ void k_hist(const int* __restrict__ dst_pos) {
    int i = blockIdx.x * blockDim.x + threadIdx.x;
    if (i < Ln * En) {
        int l = i / En;
        atomicAdd(&g_cnt[l * Un + dst_pos[i]], 1);
    }
}

// Exclusive scan of counts -> offsets. Block per layer; 20 counts/thread, shuffle scan.
__global__ void k_scan() {
    int l = blockIdx.x;
    const int* c = g_cnt + l * Un;
    int* o = g_off + l * (Un + 1);
    int t = threadIdx.x;
    int lane = t & 31, wid = t >> 5;
    int base = t * 20;
    int cnt[20];
    int s = 0;
    #pragma unroll
    for (int i = 0; i < 20; i++) {
        int idx = base + i;
        cnt[i] = (idx < Un) ? c[idx] : 0;
        s += cnt[i];
    }
    // inclusive warp scan of per-thread sums
    int v = s;
    #pragma unroll
    for (int d = 1; d < 32; d <<= 1) {
        int w = __shfl_up_sync(0xffffffffu, v, d);
        if (lane >= d) v += w;
    }
    __shared__ int wsum[32];
    if (lane == 31) wsum[wid] = v;
    __syncthreads();
    if (wid == 0) {
        int wv = wsum[lane];
        #pragma unroll
        for (int d = 1; d < 32; d <<= 1) {
            int w = __shfl_up_sync(0xffffffffu, wv, d);
            if (lane >= d) wv += w;
        }
        wsum[lane] = wv;
    }
    __syncthreads();
    int run = v - s + (wid > 0 ? wsum[wid - 1] : 0);   // exclusive prefix for this thread
    #pragma unroll
    for (int i = 0; i < 20; i++) {
        int idx = base + i;
        if (idx < Un) {
            o[idx] = run;
            run += cnt[i];
        }
    }
    if (t == 1023) o[Un] = run;
}

__global__ void k_fill(const int* __restrict__ dst_pos) {
    int i = blockIdx.x * blockDim.x + threadIdx.x;
    if (i < Ln * En) {
        int l = i / En;
        int e = i - l * En;
        int u = dst_pos[i];
        int slot = g_off[l * (Un + 1) + u] + atomicAdd(&g_cur[l * Un + u], 1);
        g_csr[l * En + slot] = e;
    }
}

// Sort each bucket by edge id (deterministic sum order), map edge id -> src node,
// then compact to alive srcs (dead rows are exactly zero -> dropping is bit-exact).
__global__ void k_sortconv(const int* __restrict__ src) {
    int gid = blockIdx.x * blockDim.x + threadIdx.x;
    if (gid >= Ln * Un) return;
    int l = gid / Un;
    int u = gid - l * Un;
    int* seg = g_csr + l * En;
    int lo = g_off[l * (Un + 1) + u];
    int hi = g_off[l * (Un + 1) + u + 1];
    for (int i = lo + 1; i < hi; i++) {
        int key = seg[i];
        int j = i - 1;
        while (j >= lo && seg[j] > key) { seg[j + 1] = seg[j]; j--; }
        seg[j + 1] = key;
    }
    const int* sl = src + l * En;
    int w = lo;
    for (int i = lo; i < hi; i++) {
        int s = sl[seg[i]];
        if (g_first[s] < l) seg[w++] = s;   // alive before layer l
        else if (w != i) { /* hole */ }
    }
    // rewrite pass above both converts and compacts; but conversion must not
    // overwrite entries not yet read — w <= i always, safe.
    g_len[l * Un + u] = w - lo;
}

// Edge-sum: agg[u][half] = sum_(alive edges) fp32(h[src][half]).
// Block covers TWO dst slots: 128 threads = 2 x (64 threads x 8 elements).
__global__ __launch_bounds__(128) void k_gsum(int l) {
    int t = threadIdx.x;
    int u = blockIdx.x * 2 + (t >> 6);
    int tt = t & 63;
    size_t col = ((size_t)blockIdx.y << 9) + (tt << 3);   // element offset (halfs)

    int lo = g_off[l * (Un + 1) + u];
    int n = g_len[l * Un + u];
    const int* e = g_csr + l * En + lo;

    float a0 = 0.f, a1 = 0.f, a2 = 0.f, a3 = 0.f;
    float a4 = 0.f, a5 = 0.f, a6 = 0.f, a7 = 0.f;
    uint4 p0, p1;
    if (n > 0) p0 = *(const uint4*)(g_h + (size_t)e[0] * ND + col);
    if (n > 1) p1 = *(const uint4*)(g_h + (size_t)e[1] * ND + col);
    for (int i = 0; i < n; i++) {
        uint4 d = p0;
        p0 = p1;
        if (i + 2 < n) p1 = *(const uint4*)(g_h + (size_t)e[i + 2] * ND + col);
        float2 f0 = __half22float2(*(const __half2*)&d.x);
        float2 f1 = __half22float2(*(const __half2*)&d.y);
        float2 f2 = __half22float2(*(const __half2*)&d.z);
        float2 f3 = __half22float2(*(const __half2*)&d.w);
        a0 += f0.x; a1 += f0.y; a2 += f1.x; a3 += f1.y;
        a4 += f2.x; a5 += f2.y; a6 += f3.x; a7 += f3.y;
    }

    float* dst = g_agg + (size_t)u * ND + col;
    *(float4*)dst       = make_float4(a0, a1, a2, a3);
    *(float4*)(dst + 4) = make_float4(a4, a5, a6, a7);
}

// Streaming transform of the 20K agg rows: h[dstu[u]] = fp16(tanh(agg[u] @ W + bias)).
__global__ __launch_bounds__(256, 2) void k_xf2(int l, const float* __restrict__ W,
                                                const float* __restrict__ bias,
                                                const int* __restrict__ dstu) {
    const float* Wl = W + l * Dn * Dn;
    int t = threadIdx.x;
    int b = t >> 2, q = t & 3;
    int j0 = q << 2;
    int u0 = blockIdx.x * NPB;

    unsigned long long w01[16], w23[16];
    #pragma unroll
    for (int k = 0; k < 16; k++) {
        ulonglong2 wp = *(const ulonglong2*)(Wl + k * Dn + j0);
        w01[k] = wp.x;
        w23[k] = wp.y;
    }

    const float4* ap = (const float4*)(g_agg + (size_t)u0 * ND + (b << 4));
    float4 c0 = __ldcs(ap + 0), c1 = __ldcs(ap + 1), c2 = __ldcs(ap + 2), c3 = __ldcs(ap + 3);

    #pragma unroll
    for (int nn = 0; nn < NPB; nn++) {
        float4 v0 = c0, v1 = c1, v2 = c2, v3 = c3;
        if (nn + 1 < NPB) {
            const float4* np = (const float4*)(g_agg + (size_t)(u0 + nn + 1) * ND + (b << 4));
            c0 = __ldcs(np + 0); c1 = __ldcs(np + 1); c2 = __ldcs(np + 2); c3 = __ldcs(np + 3);
        }
        unsigned long long acc01 = 0ull, acc23 = 0ull;
        #define XF_STEP(kk, hval) { unsigned long long hk2_; \
            asm("mov.b64 %0, {%1, %1};" : "=l"(hk2_) : "f"(hval)); \
            asm("fma.rn.f32x2 %0, %1, %2, %0;" : "+l"(acc01) : "l"(hk2_), "l"(w01[kk])); \
            asm("fma.rn.f32x2 %0, %1, %2, %0;" : "+l"(acc23) : "l"(hk2_), "l"(w23[kk])); }
        XF_STEP(0,  v0.x) XF_STEP(1,  v0.y) XF_STEP(2,  v0.z) XF_STEP(3,  v0.w)
        XF_STEP(4,  v1.x) XF_STEP(5,  v1.y) XF_STEP(6,  v1.z) XF_STEP(7,  v1.w)
        XF_STEP(8,  v2.x) XF_STEP(9,  v2.y) XF_STEP(10, v2.z) XF_STEP(11, v2.w)
        XF_STEP(12, v3.x) XF_STEP(13, v3.y) XF_STEP(14, v3.z) XF_STEP(15, v3.w)
        #undef XF_STEP

        int node = dstu[u0 + nn];
        float4 bi = *(const float4*)(bias + (size_t)node * Dn + j0);
        float r0, r1, r2, r3;
        asm("mov.b64 {%0, %1}, %2;" : "=f"(r0), "=f"(r1) : "l"(acc01));
        asm("mov.b64 {%0, %1}, %2;" : "=f"(r2), "=f"(r3) : "l"(acc23));
        __half2 o01 = __floats2half2_rn(tanhf(r0 + bi.x), tanhf(r1 + bi.y));
        __half2 o23 = __floats2half2_rn(tanhf(r2 + bi.z), tanhf(r3 + bi.w));
        __half2* dst = (__half2*)(g_h + (size_t)node * ND + t * 4);
        dst[0] = o01;
        dst[1] = o23;
    }
}

// out[b,c] = sum_{r,j} h[root[r]][b][j] * W_head[c][r*16+j] + b_head[c]
__global__ void k_head(const int* __restrict__ roots, const float* __restrict__ Wh,
                       const float* __restrict__ bh, float* __restrict__ out) {
    int b = blockIdx.x;
    int t = threadIdx.x;
    float a0 = 0.f, a1 = 0.f;
    for (int i = t; i < Rn * Dn; i += 256) {
        int r = i >> 4, j = i & 15;
        float f = __half2float(g_h[(size_t)roots[r] * ND + (b << 4) + j]);
        a0 = fmaf(f, Wh[i], a0);
        a1 = fmaf(f, Wh[Rn * Dn + i], a1);
    }
    __shared__ float s0[256], s1[256];
    s0[t] = a0; s1[t] = a1;
    __syncthreads();
    for (int st = 128; st > 0; st >>= 1) {
        if (t < st) { s0[t] += s0[t + st]; s1[t] += s1[t + st]; }
        __syncthreads();
    }
    if (t == 0) {
        out[b * Cn + 0] = s0[0] + bh[0];
        out[b * Cn + 1] = s1[0] + bh[1];
    }
}

extern "C" void kernel_launch(void* const* d_in, const int* in_sizes, int n_in,
                              void* d_out, int out_size) {
    (void)in_sizes; (void)n_in; (void)out_size;
    const float* X          = (const float*)d_in[0];
    const float* w_in       = (const float*)d_in[1];
    const float* b_in       = (const float*)d_in[2];
    const float* W          = (const float*)d_in[3];
    const float* bias       = (const float*)d_in[4];
    const float* W_head     = (const float*)d_in[5];
    const float* b_head     = (const float*)d_in[6];
    const int*   gene_map   = (const int*)d_in[7];
    const int*   src        = (const int*)d_in[8];
    const int*   dst_pos    = (const int*)d_in[9];
    const int*   dst_unique = (const int*)d_in[10];
    const int*   root_ids   = (const int*)d_in[11];
    float* out = (float*)d_out;

    k_zero_int<<<(Ln * Un + 255) / 256, 256>>>();
    k_alive<<<(Gn + Ln * Un + 255) / 256, 256>>>(gene_map, dst_unique);
    k_gene<<<Gn, 256>>>(X, w_in, b_in, gene_map);

    // Batched CSR build for all 8 layers (depends only on dst_pos / src / aliveness)
    k_hist<<<(Ln * En + 255) / 256, 256>>>(dst_pos);
    k_scan<<<Ln, 1024>>>();
    k_fill<<<(Ln * En + 255) / 256, 256>>>(dst_pos);
    k_sortconv<<<(Ln * Un + 255) / 256, 256>>>(src);   // sort + node-map + alive-compact

    for (int l = 0; l < Ln; l++) {
        k_gsum<<<dim3(Un / 2, 2), 128>>>(l);           // fp16 gather, fp32 accumulate
        k_xf2<<<Un / NPB, 256>>>(l, W, bias, dst_unique + l * Un);
    }

    k_head<<<Bn, 256>>>(root_ids, W_head, b_head, out);
}

// round 12
// speedup vs baseline: 4.7051x; 1.6704x over previous
#include <cuda_runtime.h>
#include <cuda_fp16.h>
#include <cstdint>

#define Bn 64
#define Nn 50000
#define Ln 8
#define En 100000
#define Un 20000
#define Gn 20000
#define Rn 64
#define Dn 16
#define Cn 2
#define ND (Bn*Dn)   /* 1024 elements per node row */
#define NPB 8        /* agg rows per block in k_xf2 */

// Scratch (device globals: allocation-free rule). g_h zero at module load.
__device__ __half g_h[(size_t)Nn * ND];    // ~102.4 MB, [node][b][d], updated in place
__device__ float  g_agg[(size_t)Un * ND];  // ~81.9 MB fp32 edge sums (reused per layer)
__device__ int    g_csr[Ln * En];
__device__ int    g_off[Ln * (Un + 1)];
__device__ int    g_len[Ln * Un];          // post-prune bucket lengths
__device__ int    g_cnt[Ln * Un];
__device__ int    g_cur[Ln * Un];
__device__ int    g_first[Nn];             // min(-1 if gene, first dst layer); INF=127
__device__ int    g_mask[Nn];              // bitmask of layers where node is a dst
__device__ int    g_inv[Ln * Nn];          // inv[l*Nn+node] = u  (valid where mask bit set)
__device__ int    g_need[Ln * Un];         // backward-liveness flag per slot

__global__ void k_zero_int() {
    int i = blockIdx.x * blockDim.x + threadIdx.x;
    if (i < Ln * Un) { g_cnt[i] = 0; g_cur[i] = 0; g_need[i] = 0; }
    if (i < Nn) { g_first[i] = 127; g_mask[i] = 0; }
}

// Aliveness + version tables: gene nodes alive from start; dst nodes get mask bit + inv slot.
__global__ void k_alive(const int* __restrict__ gene_map, const int* __restrict__ dst_unique) {
    int i = blockIdx.x * blockDim.x + threadIdx.x;
    if (i < Gn) {
        atomicMin(&g_first[gene_map[i]], -1);
    } else if (i < Gn + Ln * Un) {
        int k = i - Gn;
        int l = k / Un;
        int u = k - l * Un;
        int node = dst_unique[k];
        atomicMin(&g_first[node], l);
        atomicOr(&g_mask[node], 1 << l);
        g_inv[l * Nn + node] = u;
    }
}

// h[gene_map[g]] = fp16( X[b,g] * w_in + b_in )
__global__ void k_gene(const float* __restrict__ X, const float* __restrict__ w_in,
                       const float* __restrict__ b_in, const int* __restrict__ gene_map) {
    int g = blockIdx.x;
    int t = threadIdx.x;
    int b = t >> 2, j0 = (t & 3) << 2;
    int node = gene_map[g];
    float x = X[(size_t)b * Gn + g];
    float4 w  = *(const float4*)(w_in + j0);
    float4 bi = *(const float4*)(b_in + j0);
    __half2 h01 = __floats2half2_rn(fmaf(x, w.x, bi.x), fmaf(x, w.y, bi.y));
    __half2 h23 = __floats2half2_rn(fmaf(x, w.z, bi.z), fmaf(x, w.w, bi.w));
    __half2* dst = (__half2*)(g_h + (size_t)node * ND + t * 4);
    dst[0] = h01;
    dst[1] = h23;
}

__global__ void k_hist(const int* __restrict__ dst_pos) {
    int i = blockIdx.x * blockDim.x + threadIdx.x;
    if (i < Ln * En) {
        int l = i / En;
        atomicAdd(&g_cnt[l * Un + dst_pos[i]], 1);
    }
}

// Exclusive scan of counts -> offsets. Block per layer; 20 counts/thread, shuffle scan.
__global__ void k_scan() {
    int l = blockIdx.x;
    const int* c = g_cnt + l * Un;
    int* o = g_off + l * (Un + 1);
    int t = threadIdx.x;
    int lane = t & 31, wid = t >> 5;
    int base = t * 20;
    int cnt[20];
    int s = 0;
    #pragma unroll
    for (int i = 0; i < 20; i++) {
        int idx = base + i;
        cnt[i] = (idx < Un) ? c[idx] : 0;
        s += cnt[i];
    }
    int v = s;
    #pragma unroll
    for (int d = 1; d < 32; d <<= 1) {
        int w = __shfl_up_sync(0xffffffffu, v, d);
        if (lane >= d) v += w;
    }
    __shared__ int wsum[32];
    if (lane == 31) wsum[wid] = v;
    __syncthreads();
    if (wid == 0) {
        int wv = wsum[lane];
        #pragma unroll
        for (int d = 1; d < 32; d <<= 1) {
            int w = __shfl_up_sync(0xffffffffu, wv, d);
            if (lane >= d) wv += w;
        }
        wsum[lane] = wv;
    }
    __syncthreads();
    int run = v - s + (wid > 0 ? wsum[wid - 1] : 0);
    #pragma unroll
    for (int i = 0; i < 20; i++) {
        int idx = base + i;
        if (idx < Un) {
            o[idx] = run;
            run += cnt[i];
        }
    }
    if (t == 1023) o[Un] = run;
}

__global__ void k_fill(const int* __restrict__ dst_pos) {
    int i = blockIdx.x * blockDim.x + threadIdx.x;
    if (i < Ln * En) {
        int l = i / En;
        int e = i - l * En;
        int u = dst_pos[i];
        int slot = g_off[l * (Un + 1) + u] + atomicAdd(&g_cur[l * Un + u], 1);
        g_csr[l * En + slot] = e;
    }
}

// Sort bucket by edge id (deterministic order), map edge -> src node, compact to alive.
__global__ void k_sortconv(const int* __restrict__ src) {
    int gid = blockIdx.x * blockDim.x + threadIdx.x;
    if (gid >= Ln * Un) return;
    int l = gid / Un;
    int u = gid - l * Un;
    int* seg = g_csr + l * En;
    int lo = g_off[l * (Un + 1) + u];
    int hi = g_off[l * (Un + 1) + u + 1];
    for (int i = lo + 1; i < hi; i++) {
        int key = seg[i];
        int j = i - 1;
        while (j >= lo && seg[j] > key) { seg[j + 1] = seg[j]; j--; }
        seg[j + 1] = key;
    }
    const int* sl = src + l * En;
    int w = lo;
    for (int i = lo; i < hi; i++) {
        int s = sl[seg[i]];
        if (g_first[s] < l) seg[w++] = s;   // alive before layer l (w <= i: safe in-place)
    }
    g_len[l * Un + u] = w - lo;
}

// Seed backward liveness: each root's FINAL version slot is needed.
__global__ void k_seed(const int* __restrict__ roots) {
    int r = threadIdx.x;
    if (r >= Rn) return;
    int node = roots[r];
    int m = g_mask[node];
    if (m) {
        int k = 31 - __clz((unsigned)m);
        g_need[k * Un + g_inv[k * Nn + node]] = 1;
    }
}

// Backward pass for layer l: each needed slot marks the versions it reads.
__global__ void k_back(int l) {
    int u = blockIdx.x * blockDim.x + threadIdx.x;
    if (u >= Un) return;
    if (!g_need[l * Un + u]) return;
    int lo = g_off[l * (Un + 1) + u];
    int n = g_len[l * Un + u];
    const int* e = g_csr + l * En + lo;
    unsigned below = (1u << l) - 1u;
    for (int i = 0; i < n; i++) {
        int s = e[i];
        unsigned m = (unsigned)g_mask[s] & below;
        if (m) {
            int k = 31 - __clz(m);
            g_need[k * Un + g_inv[k * Nn + s]] = 1;   // idempotent plain store
        }
    }
}

// Edge-sum: agg[u][half] = sum_(alive edges) fp32(h[src][half]). Skips unneeded slots.
// Block covers TWO dst slots: 128 threads = 2 x (64 threads x 8 elements).
__global__ __launch_bounds__(128) void k_gsum(int l) {
    int t = threadIdx.x;
    int u = blockIdx.x * 2 + (t >> 6);
    if (!g_need[l * Un + u]) return;     // warp-uniform exit (warps 0-1 = dstA, 2-3 = dstB)
    int tt = t & 63;
    size_t col = ((size_t)blockIdx.y << 9) + (tt << 3);

    int lo = g_off[l * (Un + 1) + u];
    int n = g_len[l * Un + u];
    const int* e = g_csr + l * En + lo;

    float a0 = 0.f, a1 = 0.f, a2 = 0.f, a3 = 0.f;
    float a4 = 0.f, a5 = 0.f, a6 = 0.f, a7 = 0.f;
    uint4 p0, p1;
    if (n > 0) p0 = *(const uint4*)(g_h + (size_t)e[0] * ND + col);
    if (n > 1) p1 = *(const uint4*)(g_h + (size_t)e[1] * ND + col);
    for (int i = 0; i < n; i++) {
        uint4 d = p0;
        p0 = p1;
        if (i + 2 < n) p1 = *(const uint4*)(g_h + (size_t)e[i + 2] * ND + col);
        float2 f0 = __half22float2(*(const __half2*)&d.x);
        float2 f1 = __half22float2(*(const __half2*)&d.y);
        float2 f2 = __half22float2(*(const __half2*)&d.z);
        float2 f3 = __half22float2(*(const __half2*)&d.w);
        a0 += f0.x; a1 += f0.y; a2 += f1.x; a3 += f1.y;
        a4 += f2.x; a5 += f2.y; a6 += f3.x; a7 += f3.y;
    }

    float* dst = g_agg + (size_t)u * ND + col;
    *(float4*)dst       = make_float4(a0, a1, a2, a3);
    *(float4*)(dst + 4) = make_float4(a4, a5, a6, a7);
}

// Transform needed agg rows: h[dstu[u]] = fp16(tanh(agg[u] @ W + bias)).
__global__ __launch_bounds__(256, 2) void k_xf2(int l, const float* __restrict__ W,
                                                const float* __restrict__ bias,
                                                const int* __restrict__ dstu) {
    const float* Wl = W + l * Dn * Dn;
    int t = threadIdx.x;
    int b = t >> 2, q = t & 3;
    int j0 = q << 2;
    int u0 = blockIdx.x * NPB;

    unsigned long long w01[16], w23[16];
    #pragma unroll
    for (int k = 0; k < 16; k++) {
        ulonglong2 wp = *(const ulonglong2*)(Wl + k * Dn + j0);
        w01[k] = wp.x;
        w23[k] = wp.y;
    }

    #pragma unroll
    for (int nn = 0; nn < NPB; nn++) {
        int u = u0 + nn;
        if (!g_need[l * Un + u]) continue;   // block-uniform branch
        const float4* ap = (const float4*)(g_agg + (size_t)u * ND + (b << 4));
        float4 v0 = __ldcs(ap + 0), v1 = __ldcs(ap + 1);
        float4 v2 = __ldcs(ap + 2), v3 = __ldcs(ap + 3);

        unsigned long long acc01 = 0ull, acc23 = 0ull;
        #define XF_STEP(kk, hval) { unsigned long long hk2_; \
            asm("mov.b64 %0, {%1, %1};" : "=l"(hk2_) : "f"(hval)); \
            asm("fma.rn.f32x2 %0, %1, %2, %0;" : "+l"(acc01) : "l"(hk2_), "l"(w01[kk])); \
            asm("fma.rn.f32x2 %0, %1, %2, %0;" : "+l"(acc23) : "l"(hk2_), "l"(w23[kk])); }
        XF_STEP(0,  v0.x) XF_STEP(1,  v0.y) XF_STEP(2,  v0.z) XF_STEP(3,  v0.w)
        XF_STEP(4,  v1.x) XF_STEP(5,  v1.y) XF_STEP(6,  v1.z) XF_STEP(7,  v1.w)
        XF_STEP(8,  v2.x) XF_STEP(9,  v2.y) XF_STEP(10, v2.z) XF_STEP(11, v2.w)
        XF_STEP(12, v3.x) XF_STEP(13, v3.y) XF_STEP(14, v3.z) XF_STEP(15, v3.w)
        #undef XF_STEP

        int node = dstu[u];
        float4 bi = *(const float4*)(bias + (size_t)node * Dn + j0);
        float r0, r1, r2, r3;
        asm("mov.b64 {%0, %1}, %2;" : "=f"(r0), "=f"(r1) : "l"(acc01));
        asm("mov.b64 {%0, %1}, %2;" : "=f"(r2), "=f"(r3) : "l"(acc23));
        __half2 o01 = __floats2half2_rn(tanhf(r0 + bi.x), tanhf(r1 + bi.y));
        __half2 o23 = __floats2half2_rn(tanhf(r2 + bi.z), tanhf(r3 + bi.w));
        __half2* dst = (__half2*)(g_h + (size_t)node * ND + t * 4);
        dst[0] = o01;
        dst[1] = o23;
    }
}

// out[b,c] = sum_{r,j} h[root[r]][b][j] * W_head[c][r*16+j] + b_head[c]
__global__ void k_head(const int* __restrict__ roots, const float* __restrict__ Wh,
                       const float* __restrict__ bh, float* __restrict__ out) {
    int b = blockIdx.x;
    int t = threadIdx.x;
    float a0 = 0.f, a1 = 0.f;
    for (int i = t; i < Rn * Dn; i += 256) {
        int r = i >> 4, j = i & 15;
        float f = __half2float(g_h[(size_t)roots[r] * ND + (b << 4) + j]);
        a0 = fmaf(f, Wh[i], a0);
        a1 = fmaf(f, Wh[Rn * Dn + i], a1);
    }
    __shared__ float s0[256], s1[256];
    s0[t] = a0; s1[t] = a1;
    __syncthreads();
    for (int st = 128; st > 0; st >>= 1) {
        if (t < st) { s0[t] += s0[t + st]; s1[t] += s1[t + st]; }
        __syncthreads();
    }
    if (t == 0) {
        out[b * Cn + 0] = s0[0] + bh[0];
        out[b * Cn + 1] = s1[0] + bh[1];
    }
}

extern "C" void kernel_launch(void* const* d_in, const int* in_sizes, int n_in,
                              void* d_out, int out_size) {
    (void)in_sizes; (void)n_in; (void)out_size;
    const float* X          = (const float*)d_in[0];
    const float* w_in       = (const float*)d_in[1];
    const float* b_in       = (const float*)d_in[2];
    const float* W          = (const float*)d_in[3];
    const float* bias       = (const float*)d_in[4];
    const float* W_head     = (const float*)d_in[5];
    const float* b_head     = (const float*)d_in[6];
    const int*   gene_map   = (const int*)d_in[7];
    const int*   src        = (const int*)d_in[8];
    const int*   dst_pos    = (const int*)d_in[9];
    const int*   dst_unique = (const int*)d_in[10];
    const int*   root_ids   = (const int*)d_in[11];
    float* out = (float*)d_out;

    k_zero_int<<<(Ln * Un + 255) / 256, 256>>>();
    k_alive<<<(Gn + Ln * Un + 255) / 256, 256>>>(gene_map, dst_unique);
    k_gene<<<Gn, 256>>>(X, w_in, b_in, gene_map);

    // Batched CSR build for all 8 layers
    k_hist<<<(Ln * En + 255) / 256, 256>>>(dst_pos);
    k_scan<<<Ln, 1024>>>();
    k_fill<<<(Ln * En + 255) / 256, 256>>>(dst_pos);
    k_sortconv<<<(Ln * Un + 255) / 256, 256>>>(src);   // sort + node-map + alive-compact

    // Backward liveness: only slots whose versions reach the head output.
    k_seed<<<1, 64>>>(root_ids);
    for (int l = Ln - 1; l >= 0; l--)
        k_back<<<(Un + 255) / 256, 256>>>(l);

    for (int l = 0; l < Ln; l++) {
        k_gsum<<<dim3(Un / 2, 2), 128>>>(l);           // needed slots only
        k_xf2<<<Un / NPB, 256>>>(l, W, bias, dst_unique + l * Un);
    }

    k_head<<<Bn, 256>>>(root_ids, W_head, b_head, out);
}

// round 13
// speedup vs baseline: 7.4899x; 1.5919x over previous
#include <cuda_runtime.h>
#include <cuda_fp16.h>
#include <cstdint>

#define Bn 64
#define Nn 50000
#define Ln 8
#define En 100000
#define Un 20000
#define Gn 20000
#define Rn 64
#define Dn 16
#define Cn 2
#define ND (Bn*Dn)     /* 1024 elements per row */
#define NBLK 1024      /* k_layer grid.x */

// Scratch (device globals; zero at module load).
__device__ __half g_h[(size_t)Nn * ND];        // ~102 MB initial node values
__device__ __half g_v[(size_t)Ln * Un * ND];   // ~328 MB version rows [l][u][b][d]
__device__ int    g_csr[Ln * En];              // resolved absolute row ids after setup
__device__ int    g_off[Ln * (Un + 1)];
__device__ int    g_len[Ln * Un];
__device__ int    g_cnt[Ln * Un];
__device__ int    g_cur[Ln * Un];
__device__ int    g_first[Nn];                 // -1 gene, else first dst layer; 127=never
__device__ int    g_mask[Nn];                  // layers where node is a dst
__device__ int    g_inv[Ln * Nn];              // inv[l][node] = u
__device__ int    g_need[Ln * Un];             // backward liveness
__device__ int    g_list[Ln * Un];             // compacted needed u per layer
__device__ int    g_ncnt[Ln];
__device__ int    g_rootrow[Rn];               // absolute row per root

__global__ void k_zero_int() {
    int i = blockIdx.x * blockDim.x + threadIdx.x;
    if (i < Ln * Un) { g_cnt[i] = 0; g_cur[i] = 0; g_need[i] = 0; }
    if (i < Nn) { g_first[i] = 127; g_mask[i] = 0; }
}

__global__ void k_alive(const int* __restrict__ gene_map, const int* __restrict__ dst_unique) {
    int i = blockIdx.x * blockDim.x + threadIdx.x;
    if (i < Gn) {
        atomicMin(&g_first[gene_map[i]], -1);
    } else if (i < Gn + Ln * Un) {
        int k = i - Gn;
        int l = k / Un;
        int u = k - l * Un;
        int node = dst_unique[k];
        atomicMin(&g_first[node], l);
        atomicOr(&g_mask[node], 1 << l);
        g_inv[l * Nn + node] = u;
    }
}

__global__ void k_gene(const float* __restrict__ X, const float* __restrict__ w_in,
                       const float* __restrict__ b_in, const int* __restrict__ gene_map) {
    int g = blockIdx.x;
    int t = threadIdx.x;
    int b = t >> 2, j0 = (t & 3) << 2;
    int node = gene_map[g];
    float x = X[(size_t)b * Gn + g];
    float4 w  = *(const float4*)(w_in + j0);
    float4 bi = *(const float4*)(b_in + j0);
    __half2 h01 = __floats2half2_rn(fmaf(x, w.x, bi.x), fmaf(x, w.y, bi.y));
    __half2 h23 = __floats2half2_rn(fmaf(x, w.z, bi.z), fmaf(x, w.w, bi.w));
    __half2* dst = (__half2*)(g_h + (size_t)node * ND + t * 4);
    dst[0] = h01;
    dst[1] = h23;
}

__global__ void k_hist(const int* __restrict__ dst_pos) {
    int i = blockIdx.x * blockDim.x + threadIdx.x;
    if (i < Ln * En) {
        int l = i / En;
        atomicAdd(&g_cnt[l * Un + dst_pos[i]], 1);
    }
}

__global__ void k_scan() {
    int l = blockIdx.x;
    const int* c = g_cnt + l * Un;
    int* o = g_off + l * (Un + 1);
    int t = threadIdx.x;
    int lane = t & 31, wid = t >> 5;
    int base = t * 20;
    int cnt[20];
    int s = 0;
    #pragma unroll
    for (int i = 0; i < 20; i++) {
        int idx = base + i;
        cnt[i] = (idx < Un) ? c[idx] : 0;
        s += cnt[i];
    }
    int v = s;
    #pragma unroll
    for (int d = 1; d < 32; d <<= 1) {
        int w = __shfl_up_sync(0xffffffffu, v, d);
        if (lane >= d) v += w;
    }
    __shared__ int wsum[32];
    if (lane == 31) wsum[wid] = v;
    __syncthreads();
    if (wid == 0) {
        int wv = wsum[lane];
        #pragma unroll
        for (int d = 1; d < 32; d <<= 1) {
            int w = __shfl_up_sync(0xffffffffu, wv, d);
            if (lane >= d) wv += w;
        }
        wsum[lane] = wv;
    }
    __syncthreads();
    int run = v - s + (wid > 0 ? wsum[wid - 1] : 0);
    #pragma unroll
    for (int i = 0; i < 20; i++) {
        int idx = base + i;
        if (idx < Un) {
            o[idx] = run;
            run += cnt[i];
        }
    }
    if (t == 1023) o[Un] = run;
}

__global__ void k_fill(const int* __restrict__ dst_pos) {
    int i = blockIdx.x * blockDim.x + threadIdx.x;
    if (i < Ln * En) {
        int l = i / En;
        int e = i - l * En;
        int u = dst_pos[i];
        int slot = g_off[l * (Un + 1) + u] + atomicAdd(&g_cur[l * Un + u], 1);
        g_csr[l * En + slot] = e;
    }
}

// Sort bucket (deterministic order), map edge -> src node -> absolute ROW id
// (initial row in g_h, or version row Nn + k*Un + u'), compact to alive srcs.
__global__ void k_sortconv(const int* __restrict__ src) {
    int gid = blockIdx.x * blockDim.x + threadIdx.x;
    if (gid >= Ln * Un) return;
    int l = gid / Un;
    int u = gid - l * Un;
    int* seg = g_csr + l * En;
    int lo = g_off[l * (Un + 1) + u];
    int hi = g_off[l * (Un + 1) + u + 1];
    for (int i = lo + 1; i < hi; i++) {
        int key = seg[i];
        int j = i - 1;
        while (j >= lo && seg[j] > key) { seg[j + 1] = seg[j]; j--; }
        seg[j + 1] = key;
    }
    const int* sl = src + l * En;
    unsigned below = (1u << l) - 1u;
    int w = lo;
    for (int i = lo; i < hi; i++) {
        int s = sl[seg[i]];
        if (g_first[s] < l) {
            unsigned m = (unsigned)g_mask[s] & below;
            int row;
            if (m) {
                int k = 31 - __clz(m);
                row = Nn + k * Un + g_inv[k * Nn + s];
            } else {
                row = s;
            }
            seg[w++] = row;     // w <= i: safe in-place
        }
    }
    g_len[l * Un + u] = w - lo;
}

// Seed: each root's final version slot is needed; record its absolute row for k_head.
__global__ void k_seed(const int* __restrict__ roots) {
    int r = threadIdx.x;
    if (r >= Rn) return;
    int node = roots[r];
    int m = g_mask[node];
    if (m) {
        int k = 31 - __clz((unsigned)m);
        int u = g_inv[k * Nn + node];
        g_need[k * Un + u] = 1;
        g_rootrow[r] = Nn + k * Un + u;
    } else {
        g_rootrow[r] = node;
    }
}

// Backward: needed slot marks every version row it reads.
__global__ void k_back(int l) {
    int u = blockIdx.x * blockDim.x + threadIdx.x;
    if (u >= Un) return;
    if (!g_need[l * Un + u]) return;
    int lo = g_off[l * (Un + 1) + u];
    int n = g_len[l * Un + u];
    const int* e = g_csr + l * En + lo;
    for (int i = 0; i < n; i++) {
        int row = e[i];
        if (row >= Nn) g_need[row - Nn] = 1;
    }
}

// Compact needed u's into per-layer lists (u ascending). Block per layer.
__global__ void k_compact() {
    int l = blockIdx.x;
    const int* nd = g_need + l * Un;
    int* lst = g_list + l * Un;
    int t = threadIdx.x;
    int lane = t & 31, wid = t >> 5;
    int base = t * 20;
    int flg[20];
    int s = 0;
    #pragma unroll
    for (int i = 0; i < 20; i++) {
        int idx = base + i;
        flg[i] = (idx < Un) ? nd[idx] : 0;
        s += flg[i];
    }
    int v = s;
    #pragma unroll
    for (int d = 1; d < 32; d <<= 1) {
        int w = __shfl_up_sync(0xffffffffu, v, d);
        if (lane >= d) v += w;
    }
    __shared__ int wsum[32];
    if (lane == 31) wsum[wid] = v;
    __syncthreads();
    if (wid == 0) {
        int wv = wsum[lane];
        #pragma unroll
        for (int d = 1; d < 32; d <<= 1) {
            int w = __shfl_up_sync(0xffffffffu, wv, d);
            if (lane >= d) wv += w;
        }
        wsum[lane] = wv;
    }
    __syncthreads();
    int run = v - s + (wid > 0 ? wsum[wid - 1] : 0);
    #pragma unroll
    for (int i = 0; i < 20; i++) {
        int idx = base + i;
        if (idx < Un && flg[i]) lst[run++] = idx;
    }
    if (t == 1023) g_ncnt[l] = run;
}

// Fused layer kernel: for each needed slot u (strided over g_list):
//   S[b][k] = sum_edges row[b][k]  (fp16 rows, fp32 accumulate, 16B/edge/thread)
//   out[b][j] = tanh( sum_k S[k]*W[k][j] + bias[j] ) -> g_v[l][u]  (fp16)
// Thread tt of 64 covers (b = y*32 + tt/2, k-half = (tt&1)*8). Pair-shuffle combines halves.
__global__ __launch_bounds__(128) void k_layer(int l, const float* __restrict__ W,
                                               const float* __restrict__ bias,
                                               const int* __restrict__ dstu) {
    __shared__ float sW[256];
    __shared__ int scnt;
    int t = threadIdx.x;
    if (t == 0) scnt = g_ncnt[l];
    const float* Wl = W + l * Dn * Dn;
    sW[t] = Wl[t];
    sW[t + 128] = Wl[t + 128];
    __syncthreads();
    int cnt = scnt;

    int half = t >> 6;
    int tt = t & 63;
    int kh = tt & 1;                       // 0: k 0..7, 1: k 8..15
    int k0 = kh << 3;
    size_t col = ((size_t)blockIdx.y << 9) + ((size_t)tt << 3);
    const unsigned long long* sW64 = (const unsigned long long*)sW;

    for (int it = blockIdx.x * 2 + half; it < cnt; it += NBLK * 2) {
        int u = g_list[l * Un + it];
        int lo = g_off[l * (Un + 1) + u];
        int n = g_len[l * Un + u];
        const int* e = g_csr + l * En + lo;

        // Gather-sum this thread's 8 elements (b, k0..k0+7) over edges.
        float a[8] = {0.f, 0.f, 0.f, 0.f, 0.f, 0.f, 0.f, 0.f};
        uint4 p0, p1;
        if (n > 0) {
            int r = e[0];
            const __half* bp = (r < Nn) ? (g_h + (size_t)r * ND) : (g_v + (size_t)(r - Nn) * ND);
            p0 = *(const uint4*)(bp + col);
        }
        if (n > 1) {
            int r = e[1];
            const __half* bp = (r < Nn) ? (g_h + (size_t)r * ND) : (g_v + (size_t)(r - Nn) * ND);
            p1 = *(const uint4*)(bp + col);
        }
        for (int i = 0; i < n; i++) {
            uint4 d = p0;
            p0 = p1;
            if (i + 2 < n) {
                int r = e[i + 2];
                const __half* bp = (r < Nn) ? (g_h + (size_t)r * ND) : (g_v + (size_t)(r - Nn) * ND);
                p1 = *(const uint4*)(bp + col);
            }
            float2 f0 = __half22float2(*(const __half2*)&d.x);
            float2 f1 = __half22float2(*(const __half2*)&d.y);
            float2 f2 = __half22float2(*(const __half2*)&d.z);
            float2 f3 = __half22float2(*(const __half2*)&d.w);
            a[0] += f0.x; a[1] += f0.y; a[2] += f1.x; a[3] += f1.y;
            a[4] += f2.x; a[5] += f2.y; a[6] += f3.x; a[7] += f3.y;
        }

        // Partial transform: all 16 j over this thread's 8 k's.
        unsigned long long acc[8];
        #pragma unroll
        for (int jp = 0; jp < 8; jp++) acc[jp] = 0ull;
        #pragma unroll
        for (int kk = 0; kk < 8; kk++) {
            unsigned long long s2;
            asm("mov.b64 %0, {%1, %1};" : "=l"(s2) : "f"(a[kk]));
            int rb = (k0 + kk) << 3;   // u64 index of W row
            #pragma unroll
            for (int jp = 0; jp < 8; jp++) {
                asm("fma.rn.f32x2 %0, %1, %2, %0;" : "+l"(acc[jp]) : "l"(s2), "l"(sW64[rb + jp]));
            }
        }

        // Pair exchange: my output j-half = k0..k0+7 (acc[kh*4 .. +4]); partner supplies
        // the other k-half's partial for the same j's.
        int mb = kh << 2, ob = (kh ^ 1) << 2;
        float r[8];
        #pragma unroll
        for (int i = 0; i < 4; i++) {
            unsigned long long mine  = acc[mb + i];
            unsigned long long other = __shfl_xor_sync(0xffffffffu, acc[ob + i], 1);
            float mlo, mhi, olo, ohi;
            asm("mov.b64 {%0, %1}, %2;" : "=f"(mlo), "=f"(mhi) : "l"(mine));
            asm("mov.b64 {%0, %1}, %2;" : "=f"(olo), "=f"(ohi) : "l"(other));
            r[i * 2]     = mlo + olo;
            r[i * 2 + 1] = mhi + ohi;
        }

        int node = dstu[u];
        float4 b0 = *(const float4*)(bias + (size_t)node * Dn + k0);
        float4 b1 = *(const float4*)(bias + (size_t)node * Dn + k0 + 4);
        __half2 o0 = __floats2half2_rn(tanhf(r[0] + b0.x), tanhf(r[1] + b0.y));
        __half2 o1 = __floats2half2_rn(tanhf(r[2] + b0.z), tanhf(r[3] + b0.w));
        __half2 o2 = __floats2half2_rn(tanhf(r[4] + b1.x), tanhf(r[5] + b1.y));
        __half2 o3 = __floats2half2_rn(tanhf(r[6] + b1.z), tanhf(r[7] + b1.w));
        __half2* dst = (__half2*)(g_v + ((size_t)(l * Un + u)) * ND + col);
        dst[0] = o0; dst[1] = o1; dst[2] = o2; dst[3] = o3;
    }
}

// out[b,c] = sum_{r,j} val(root r)[b][j] * W_head[c][r*16+j] + b_head[c]
__global__ void k_head(const float* __restrict__ Wh, const float* __restrict__ bh,
                       float* __restrict__ out) {
    int b = blockIdx.x;
    int t = threadIdx.x;
    float a0 = 0.f, a1 = 0.f;
    for (int i = t; i < Rn * Dn; i += 256) {
        int r = i >> 4, j = i & 15;
        int row = g_rootrow[r];
        const __half* bp = (row < Nn) ? (g_h + (size_t)row * ND) : (g_v + (size_t)(row - Nn) * ND);
        float f = __half2float(bp[(b << 4) + j]);
        a0 = fmaf(f, Wh[i], a0);
        a1 = fmaf(f, Wh[Rn * Dn + i], a1);
    }
    __shared__ float s0[256], s1[256];
    s0[t] = a0; s1[t] = a1;
    __syncthreads();
    for (int st = 128; st > 0; st >>= 1) {
        if (t < st) { s0[t] += s0[t + st]; s1[t] += s1[t + st]; }
        __syncthreads();
    }
    if (t == 0) {
        out[b * Cn + 0] = s0[0] + bh[0];
        out[b * Cn + 1] = s1[0] + bh[1];
    }
}

extern "C" void kernel_launch(void* const* d_in, const int* in_sizes, int n_in,
                              void* d_out, int out_size) {
    (void)in_sizes; (void)n_in; (void)out_size;
    const float* X          = (const float*)d_in[0];
    const float* w_in       = (const float*)d_in[1];
    const float* b_in       = (const float*)d_in[2];
    const float* W          = (const float*)d_in[3];
    const float* bias       = (const float*)d_in[4];
    const float* W_head     = (const float*)d_in[5];
    const float* b_head     = (const float*)d_in[6];
    const int*   gene_map   = (const int*)d_in[7];
    const int*   src        = (const int*)d_in[8];
    const int*   dst_pos    = (const int*)d_in[9];
    const int*   dst_unique = (const int*)d_in[10];
    const int*   root_ids   = (const int*)d_in[11];
    float* out = (float*)d_out;

    k_zero_int<<<(Ln * Un + 255) / 256, 256>>>();
    k_alive<<<(Gn + Ln * Un + 255) / 256, 256>>>(gene_map, dst_unique);
    k_gene<<<Gn, 256>>>(X, w_in, b_in, gene_map);

    // CSR build (all layers batched)
    k_hist<<<(Ln * En + 255) / 256, 256>>>(dst_pos);
    k_scan<<<Ln, 1024>>>();
    k_fill<<<(Ln * En + 255) / 256, 256>>>(dst_pos);
    k_sortconv<<<(Ln * Un + 255) / 256, 256>>>(src);   // sort + row-resolve + alive-compact

    // Backward liveness + work-list compaction
    k_seed<<<1, 64>>>(root_ids);
    for (int l = Ln - 1; l >= 0; l--)
        k_back<<<(Un + 255) / 256, 256>>>(l);
    k_compact<<<Ln, 1024>>>();

    // One fused kernel per layer over compacted work lists
    for (int l = 0; l < Ln; l++)
        k_layer<<<dim3(NBLK, 2), 128>>>(l, W, bias, dst_unique + l * Un);

    k_head<<<Bn, 256>>>(W_head, b_head, out);
}